// round 1
// baseline (speedup 1.0000x reference)
#include <cuda_runtime.h>
#include <math.h>

#define S_LEN 2048
#define HID_DIM 4096
#define NH 32
#define NKV 8
#define DH 128
// kv row stride
#define KVW (NKV * DH)   // 1024

// Scratch (device globals: allocation-free)
__device__ float g_q[S_LEN * HID_DIM];      // 32 MB
__device__ float g_k[S_LEN * KVW];          // 8 MB
__device__ float g_v[S_LEN * KVW];          // 8 MB
__device__ float g_attn[S_LEN * HID_DIM];   // 32 MB

// ---------------------------------------------------------------------------
// SGEMM: C[M,N] = A[M,K] @ B[K,N], all row-major fp32.
// BM=128, BN=128, BK=8, 256 threads, 8x8 per-thread register tile.
// M % 128 == 0, N % 128 == 0, K % 8 == 0 (true for all our shapes).
// ---------------------------------------------------------------------------
__global__ void __launch_bounds__(256, 2) sgemm_kernel(
    int M, int N, int K,
    const float* __restrict__ A, const float* __restrict__ B,
    float* __restrict__ C)
{
    const int BM = 128, BN = 128, BK = 8, TM = 8, TN = 8;
    __shared__ float As[BK][BM];
    __shared__ float Bs[BK][BN];

    const int tid = threadIdx.x;
    const int bx = blockIdx.x, by = blockIdx.y;

    const float* Ab = A + (size_t)by * BM * K;
    const float* Bb = B + (size_t)bx * BN;
    float* Cb = C + (size_t)by * BM * N + (size_t)bx * BN;

    const int rowA = tid >> 1, colA = (tid & 1) * 4;     // 128x8 tile, float4
    const int rowB = tid >> 5, colB = (tid & 31) * 4;    // 8x128 tile, float4
    const int tr = (tid >> 4) * TM;                      // output row base
    const int tc = (tid & 15) * TN;                      // output col base

    float acc[TM][TN];
#pragma unroll
    for (int i = 0; i < TM; i++)
#pragma unroll
        for (int j = 0; j < TN; j++) acc[i][j] = 0.f;

    for (int k0 = 0; k0 < K; k0 += BK) {
        float4 a = *(const float4*)(Ab + (size_t)rowA * K + colA);
        As[colA + 0][rowA] = a.x;
        As[colA + 1][rowA] = a.y;
        As[colA + 2][rowA] = a.z;
        As[colA + 3][rowA] = a.w;
        float4 b = *(const float4*)(Bb + (size_t)rowB * N + colB);
        *(float4*)&Bs[rowB][colB] = b;
        __syncthreads();
        Ab += BK;
        Bb += (size_t)BK * N;

#pragma unroll
        for (int k = 0; k < BK; k++) {
            float ra[TM], rb[TN];
            *(float4*)&ra[0] = *(const float4*)&As[k][tr];
            *(float4*)&ra[4] = *(const float4*)&As[k][tr + 4];
            *(float4*)&rb[0] = *(const float4*)&Bs[k][tc];
            *(float4*)&rb[4] = *(const float4*)&Bs[k][tc + 4];
#pragma unroll
            for (int i = 0; i < TM; i++)
#pragma unroll
                for (int j = 0; j < TN; j++)
                    acc[i][j] = fmaf(ra[i], rb[j], acc[i][j]);
        }
        __syncthreads();
    }

#pragma unroll
    for (int i = 0; i < TM; i++) {
#pragma unroll
        for (int j = 0; j < TN; j += 4) {
            float4 v = make_float4(acc[i][j], acc[i][j + 1], acc[i][j + 2], acc[i][j + 3]);
            *(float4*)(Cb + (size_t)(tr + i) * N + tc + j) = v;
        }
    }
}

// ---------------------------------------------------------------------------
// Flash-attention (fp32, causal, GQA). One block per (64-query tile, head).
// smem: Qst/Kst transposed [128][65] (pad 65 => conflict-free transpose write),
// Vs [64][128], Ps [64][65], row stats.
// ---------------------------------------------------------------------------
#define ATT_SMEM_FLOATS (128 * 65 * 2 + 64 * 128 + 64 * 65 + 192)
#define ATT_SMEM_BYTES (ATT_SMEM_FLOATS * 4)

__global__ void __launch_bounds__(256, 1) attn_kernel(
    const float* __restrict__ qb, const float* __restrict__ kb,
    const float* __restrict__ vb, float* __restrict__ ob)
{
    extern __shared__ float sm[];
    float* Qst  = sm;                    // [128][65]
    float* Kst  = Qst + 128 * 65;        // [128][65]
    float* Vs   = Kst + 128 * 65;        // [64][128]
    float* Ps   = Vs + 64 * 128;         // [64][65]
    float* rowM = Ps + 64 * 65;          // [64]
    float* rowL = rowM + 64;             // [64]
    float* rowC = rowL + 64;             // [64]

    const int tid = threadIdx.x;
    const int qt  = blockIdx.x;          // query tile 0..31
    const int h   = blockIdx.y;          // head 0..31
    const int kvh = h >> 2;              // GQA: 4 q heads per kv head
    const int m0  = qt * 64;
    const float scale = 0.08838834764831845f;  // 1/sqrt(128)

    // Load Q tile transposed: Qst[d][m]
    {
        const int lr = tid >> 5;             // 0..7
        const int d0 = (tid & 31) * 4;
#pragma unroll
        for (int p = 0; p < 8; p++) {
            int r = p * 8 + lr;
            float4 qv = *(const float4*)(qb + (size_t)(m0 + r) * HID_DIM + h * DH + d0);
            Qst[(d0 + 0) * 65 + r] = qv.x;
            Qst[(d0 + 1) * 65 + r] = qv.y;
            Qst[(d0 + 2) * 65 + r] = qv.z;
            Qst[(d0 + 3) * 65 + r] = qv.w;
        }
    }
    if (tid < 64) { rowM[tid] = -1e30f; rowL[tid] = 0.f; }

    const int trp = (tid >> 4) * 4;   // row base (S and PV)
    const int tcS = (tid & 15) * 4;   // S col base
    const int tcP = (tid & 15) * 8;   // PV col base

    float acc[4][8];
#pragma unroll
    for (int i = 0; i < 4; i++)
#pragma unroll
        for (int j = 0; j < 8; j++) acc[i][j] = 0.f;

    for (int jt = 0; jt <= qt; jt++) {
        __syncthreads();   // prior PV done (+ Q load visible on first iter)

        // Load K tile transposed (Kst[d][n]) and V tile (Vs[n][d])
        {
            const int lr = tid >> 5;
            const int d0 = (tid & 31) * 4;
#pragma unroll
            for (int p = 0; p < 8; p++) {
                int r = p * 8 + lr;
                size_t base = (size_t)(jt * 64 + r) * KVW + kvh * DH + d0;
                float4 kv = *(const float4*)(kb + base);
                Kst[(d0 + 0) * 65 + r] = kv.x;
                Kst[(d0 + 1) * 65 + r] = kv.y;
                Kst[(d0 + 2) * 65 + r] = kv.z;
                Kst[(d0 + 3) * 65 + r] = kv.w;
                float4 vv = *(const float4*)(vb + base);
                *(float4*)&Vs[r * 128 + d0] = vv;
            }
        }
        __syncthreads();

        // S = scale * Q K^T  (+ causal mask), into Ps
        {
            float s[4][4];
#pragma unroll
            for (int i = 0; i < 4; i++)
#pragma unroll
                for (int j = 0; j < 4; j++) s[i][j] = 0.f;

            for (int d = 0; d < 128; d++) {
                const int base = d * 65;
                float qr[4], kr[4];
#pragma unroll
                for (int i = 0; i < 4; i++) qr[i] = Qst[base + trp + i];
#pragma unroll
                for (int j = 0; j < 4; j++) kr[j] = Kst[base + tcS + j];
#pragma unroll
                for (int i = 0; i < 4; i++)
#pragma unroll
                    for (int j = 0; j < 4; j++)
                        s[i][j] = fmaf(qr[i], kr[j], s[i][j]);
            }
#pragma unroll
            for (int i = 0; i < 4; i++) {
                int gm = m0 + trp + i;
#pragma unroll
                for (int j = 0; j < 4; j++) {
                    int gn = jt * 64 + tcS + j;
                    float v = s[i][j] * scale;
                    if (gn > gm) v = -1e30f;
                    Ps[(trp + i) * 65 + tcS + j] = v;
                }
            }
        }
        __syncthreads();

        // Online softmax per row (one thread per row)
        if (tid < 64) {
            const int r = tid;
            float* pr = &Ps[r * 65];
            float mx = rowM[r];
            for (int c = 0; c < 64; c++) mx = fmaxf(mx, pr[c]);
            float corr = __expf(rowM[r] - mx);
            float sum = 0.f;
            for (int c = 0; c < 64; c++) {
                float e = __expf(pr[c] - mx);
                pr[c] = e;
                sum += e;
            }
            rowL[r] = rowL[r] * corr + sum;
            rowM[r] = mx;
            rowC[r] = corr;
        }
        __syncthreads();

        // acc = acc*corr + P V
        {
            float cr[4];
#pragma unroll
            for (int i = 0; i < 4; i++) cr[i] = rowC[trp + i];
#pragma unroll
            for (int i = 0; i < 4; i++)
#pragma unroll
                for (int j = 0; j < 8; j++) acc[i][j] *= cr[i];

            for (int n = 0; n < 64; n++) {
                float p[4];
#pragma unroll
                for (int i = 0; i < 4; i++) p[i] = Ps[(trp + i) * 65 + n];
                float4 v0 = *(const float4*)&Vs[n * 128 + tcP];
                float4 v1 = *(const float4*)&Vs[n * 128 + tcP + 4];
#pragma unroll
                for (int i = 0; i < 4; i++) {
                    acc[i][0] = fmaf(p[i], v0.x, acc[i][0]);
                    acc[i][1] = fmaf(p[i], v0.y, acc[i][1]);
                    acc[i][2] = fmaf(p[i], v0.z, acc[i][2]);
                    acc[i][3] = fmaf(p[i], v0.w, acc[i][3]);
                    acc[i][4] = fmaf(p[i], v1.x, acc[i][4]);
                    acc[i][5] = fmaf(p[i], v1.y, acc[i][5]);
                    acc[i][6] = fmaf(p[i], v1.z, acc[i][6]);
                    acc[i][7] = fmaf(p[i], v1.w, acc[i][7]);
                }
            }
        }
    }

    // Normalize and write to attn buffer [S, H*D], head h at cols h*128..
    float invl[4];
#pragma unroll
    for (int i = 0; i < 4; i++) invl[i] = 1.f / rowL[trp + i];
#pragma unroll
    for (int i = 0; i < 4; i++) {
        float* op = ob + (size_t)(m0 + trp + i) * HID_DIM + h * DH + tcP;
        float4 o0 = make_float4(acc[i][0] * invl[i], acc[i][1] * invl[i],
                                acc[i][2] * invl[i], acc[i][3] * invl[i]);
        float4 o1 = make_float4(acc[i][4] * invl[i], acc[i][5] * invl[i],
                                acc[i][6] * invl[i], acc[i][7] * invl[i]);
        *(float4*)(op + 0) = o0;
        *(float4*)(op + 4) = o1;
    }
}

// ---------------------------------------------------------------------------
// Launch: hidden -> {Q,K,V} GEMMs -> attention -> O GEMM
// Inputs: [0] hidden_states, [1] attention_mask (unused; exactly causal),
//         [2] wq, [3] wk, [4] wv, [5] wo
// ---------------------------------------------------------------------------
extern "C" void kernel_launch(void* const* d_in, const int* in_sizes, int n_in,
                              void* d_out, int out_size)
{
    const float* hidden = (const float*)d_in[0];
    const float* wq = (const float*)d_in[2];
    const float* wk = (const float*)d_in[3];
    const float* wv = (const float*)d_in[4];
    const float* wo = (const float*)d_in[5];
    float* out = (float*)d_out;

    float *qp, *kp, *vp, *ap;
    cudaGetSymbolAddress((void**)&qp, g_q);
    cudaGetSymbolAddress((void**)&kp, g_k);
    cudaGetSymbolAddress((void**)&vp, g_v);
    cudaGetSymbolAddress((void**)&ap, g_attn);

    cudaFuncSetAttribute(attn_kernel, cudaFuncAttributeMaxDynamicSharedMemorySize,
                         ATT_SMEM_BYTES);

    dim3 blk(256);
    // Q: [2048,4096] = hidden @ wq
    sgemm_kernel<<<dim3(HID_DIM / 128, S_LEN / 128), blk>>>(S_LEN, HID_DIM, HID_DIM, hidden, wq, qp);
    // K: [2048,1024]
    sgemm_kernel<<<dim3(KVW / 128, S_LEN / 128), blk>>>(S_LEN, KVW, HID_DIM, hidden, wk, kp);
    // V: [2048,1024]
    sgemm_kernel<<<dim3(KVW / 128, S_LEN / 128), blk>>>(S_LEN, KVW, HID_DIM, hidden, wv, vp);
    // Attention: grid (query tiles, heads)
    attn_kernel<<<dim3(S_LEN / 64, NH), blk, ATT_SMEM_BYTES>>>(qp, kp, vp, ap);
    // Output projection: out = attn @ wo
    sgemm_kernel<<<dim3(HID_DIM / 128, S_LEN / 128), blk>>>(S_LEN, HID_DIM, HID_DIM, ap, wo, out);
}

// round 3
// speedup vs baseline: 2.8771x; 2.8771x over previous
#include <cuda_runtime.h>
#include <cuda_bf16.h>
#include <mma.h>
#include <cstdint>
#include <math.h>

using namespace nvcuda;

#define S_LEN 2048
#define HID_DIM 4096
#define NH 32
#define NKV 8
#define DH 128
#define KVW (NKV * DH)   // 1024

// ---------------------------------------------------------------------------
// Scratch (device globals: allocation-free)
// ---------------------------------------------------------------------------
__device__ float g_q[S_LEN * HID_DIM];
__device__ float g_k[S_LEN * KVW];
__device__ float g_v[S_LEN * KVW];
__device__ float g_attn[S_LEN * HID_DIM];

__device__ __nv_bfloat16 g_hid_hi[S_LEN * HID_DIM];
__device__ __nv_bfloat16 g_hid_lo[S_LEN * HID_DIM];
__device__ __nv_bfloat16 g_at_hi[S_LEN * HID_DIM];
__device__ __nv_bfloat16 g_at_lo[S_LEN * HID_DIM];
__device__ __nv_bfloat16 g_wqT_hi[HID_DIM * HID_DIM];
__device__ __nv_bfloat16 g_wqT_lo[HID_DIM * HID_DIM];
__device__ __nv_bfloat16 g_wkT_hi[KVW * HID_DIM];
__device__ __nv_bfloat16 g_wkT_lo[KVW * HID_DIM];
__device__ __nv_bfloat16 g_wvT_hi[KVW * HID_DIM];
__device__ __nv_bfloat16 g_wvT_lo[KVW * HID_DIM];
__device__ __nv_bfloat16 g_woT_hi[HID_DIM * HID_DIM];
__device__ __nv_bfloat16 g_woT_lo[HID_DIM * HID_DIM];

// ---------------------------------------------------------------------------
// cp.async helpers (sm_80+ baseline PTX — safe on compute_103)
// ---------------------------------------------------------------------------
__device__ __forceinline__ uint32_t smem_u32(const void* p) {
    return (uint32_t)__cvta_generic_to_shared(p);
}
#define CP_ASYNC16(sa, gp) \
    asm volatile("cp.async.cg.shared.global [%0], [%1], 16;" :: "r"(sa), "l"(gp))
#define CP_COMMIT() asm volatile("cp.async.commit_group;" ::: "memory")
#define CP_WAIT(n)  asm volatile("cp.async.wait_group %0;" :: "n"(n) : "memory")

// ---------------------------------------------------------------------------
// Split fp32 -> (hi, lo) bf16, elementwise
// ---------------------------------------------------------------------------
__global__ void conv_hilo_kernel(const float* __restrict__ x,
                                 __nv_bfloat16* __restrict__ hi,
                                 __nv_bfloat16* __restrict__ lo, int n)
{
    int i = (blockIdx.x * blockDim.x + threadIdx.x) * 4;
    if (i >= n) return;
    float4 v = *(const float4*)(x + i);
    __nv_bfloat16 h0 = __float2bfloat16_rn(v.x);
    __nv_bfloat16 h1 = __float2bfloat16_rn(v.y);
    __nv_bfloat16 h2 = __float2bfloat16_rn(v.z);
    __nv_bfloat16 h3 = __float2bfloat16_rn(v.w);
    __nv_bfloat16 l0 = __float2bfloat16_rn(v.x - __bfloat162float(h0));
    __nv_bfloat16 l1 = __float2bfloat16_rn(v.y - __bfloat162float(h1));
    __nv_bfloat16 l2 = __float2bfloat16_rn(v.z - __bfloat162float(h2));
    __nv_bfloat16 l3 = __float2bfloat16_rn(v.w - __bfloat162float(h3));
    __nv_bfloat162* hp = (__nv_bfloat162*)(hi + i);
    __nv_bfloat162* lp = (__nv_bfloat162*)(lo + i);
    hp[0] = __nv_bfloat162(h0, h1); hp[1] = __nv_bfloat162(h2, h3);
    lp[0] = __nv_bfloat162(l0, l1); lp[1] = __nv_bfloat162(l2, l3);
}

// ---------------------------------------------------------------------------
// Transpose + split: B[K,N] fp32 -> Thi/Tlo[N,K] bf16
// ---------------------------------------------------------------------------
__global__ void conv_t_kernel(const float* __restrict__ B,
                              __nv_bfloat16* __restrict__ Thi,
                              __nv_bfloat16* __restrict__ Tlo, int K, int N)
{
    __shared__ float t[32][33];
    const int n0 = blockIdx.x * 32, k0 = blockIdx.y * 32;
    const int tx = threadIdx.x, ty = threadIdx.y;
#pragma unroll
    for (int i = 0; i < 32; i += 8)
        t[ty + i][tx] = B[(size_t)(k0 + ty + i) * N + n0 + tx];
    __syncthreads();
#pragma unroll
    for (int i = 0; i < 32; i += 8) {
        float v = t[tx][ty + i];
        __nv_bfloat16 h = __float2bfloat16_rn(v);
        size_t o = (size_t)(n0 + ty + i) * K + k0 + tx;
        Thi[o] = h;
        Tlo[o] = __float2bfloat16_rn(v - __bfloat162float(h));
    }
}

// ---------------------------------------------------------------------------
// bf16x3 wmma (HMMA) GEMM: C[M,N] = A[M,K] @ B[K,N], B given transposed [N,K].
// Tile 128x128x32, 8 warps (warp tile 64x32 = 4x2 wmma frags),
// smem ld=40 (80B rows -> ldmatrix conflict-free), cp.async double buffer.
// D += Ahi*Bhi + Ahi*Blo + Alo*Bhi
// ---------------------------------------------------------------------------
#define GLD 40
#define GMAT (128 * GLD * 2)          // 10240 B, one bf16 matrix tile
#define GSTAGE (4 * GMAT)             // Ahi, Alo, Bhi, Blo
#define GSMEM_TOTAL (2 * GSTAGE)      // 81920 B

__global__ void __launch_bounds__(256) gemm_bf16x3_kernel(
    const __nv_bfloat16* __restrict__ Ahi, const __nv_bfloat16* __restrict__ Alo,
    const __nv_bfloat16* __restrict__ Bhi, const __nv_bfloat16* __restrict__ Blo,
    float* __restrict__ C, int M, int N, int K)
{
    extern __shared__ char smem[];
    const int tid = threadIdx.x;
    const int wid = tid >> 5;
    const int wm = wid >> 2;          // 0..1 -> 64-row slice
    const int wn = wid & 3;           // 0..3 -> 32-col slice
    const int m0 = blockIdx.y * 128;
    const int n0 = blockIdx.x * 128;

    const int lr = tid >> 2;          // 0..63
    const int cs = (tid & 3) * 8;     // 0,8,16,24

    const uint32_t sbase = smem_u32(smem);

    // issue one stage of cp.async loads
    auto issue = [&](int it, int s) {
        const int k0 = it * 32;
        const uint32_t st = sbase + s * GSTAGE;
#pragma unroll
        for (int p = 0; p < 2; p++) {
            int row = lr + p * 64;
            uint32_t so = (uint32_t)((row * GLD + cs) * 2);
            size_t gA = (size_t)(m0 + row) * K + k0 + cs;
            size_t gB = (size_t)(n0 + row) * K + k0 + cs;
            CP_ASYNC16(st + 0 * GMAT + so, (const void*)(Ahi + gA));
            CP_ASYNC16(st + 1 * GMAT + so, (const void*)(Alo + gA));
            CP_ASYNC16(st + 2 * GMAT + so, (const void*)(Bhi + gB));
            CP_ASYNC16(st + 3 * GMAT + so, (const void*)(Blo + gB));
        }
        CP_COMMIT();
    };

    wmma::fragment<wmma::accumulator, 16, 16, 16, float> acc[4][2];
#pragma unroll
    for (int i = 0; i < 4; i++)
#pragma unroll
        for (int j = 0; j < 2; j++) wmma::fill_fragment(acc[i][j], 0.f);

    const int nIter = K >> 5;
    issue(0, 0);

    for (int it = 0; it < nIter; ++it) {
        if (it + 1 < nIter) {
            issue(it + 1, (it + 1) & 1);
            CP_WAIT(1);
        } else {
            CP_WAIT(0);
        }
        __syncthreads();

        const __nv_bfloat16* stg = (const __nv_bfloat16*)(smem + (it & 1) * GSTAGE);
        const __nv_bfloat16* As_h = stg;
        const __nv_bfloat16* As_l = stg + 128 * GLD;
        const __nv_bfloat16* Bs_h = stg + 2 * 128 * GLD;
        const __nv_bfloat16* Bs_l = stg + 3 * 128 * GLD;

#pragma unroll
        for (int ks = 0; ks < 2; ks++) {
            wmma::fragment<wmma::matrix_a, 16, 16, 16, __nv_bfloat16, wmma::row_major> ah[4], al[4];
            wmma::fragment<wmma::matrix_b, 16, 16, 16, __nv_bfloat16, wmma::col_major> bh[2], bl[2];
#pragma unroll
            for (int i = 0; i < 4; i++) {
                const int r = (wm * 64 + i * 16) * GLD + ks * 16;
                wmma::load_matrix_sync(ah[i], As_h + r, GLD);
                wmma::load_matrix_sync(al[i], As_l + r, GLD);
            }
#pragma unroll
            for (int j = 0; j < 2; j++) {
                const int r = (wn * 32 + j * 16) * GLD + ks * 16;
                wmma::load_matrix_sync(bh[j], Bs_h + r, GLD);
                wmma::load_matrix_sync(bl[j], Bs_l + r, GLD);
            }
#pragma unroll
            for (int i = 0; i < 4; i++)
#pragma unroll
                for (int j = 0; j < 2; j++) {
                    wmma::mma_sync(acc[i][j], ah[i], bh[j], acc[i][j]);
                    wmma::mma_sync(acc[i][j], ah[i], bl[j], acc[i][j]);
                    wmma::mma_sync(acc[i][j], al[i], bh[j], acc[i][j]);
                }
        }
        __syncthreads();
    }

#pragma unroll
    for (int i = 0; i < 4; i++)
#pragma unroll
        for (int j = 0; j < 2; j++) {
            float* cp = C + (size_t)(m0 + wm * 64 + i * 16) * N + n0 + wn * 32 + j * 16;
            wmma::store_matrix_sync(cp, acc[i][j], N, wmma::mem_row_major);
        }
}

// ---------------------------------------------------------------------------
// Flash-attention (fp32, causal, GQA), parallel online softmax (4 thr/row).
// ---------------------------------------------------------------------------
#define ATT_SMEM_FLOATS (128 * 65 * 2 + 64 * 128 + 64 * 65 + 192)
#define ATT_SMEM_BYTES (ATT_SMEM_FLOATS * 4)

__global__ void __launch_bounds__(256, 1) attn_kernel(
    const float* __restrict__ qb, const float* __restrict__ kb,
    const float* __restrict__ vb, float* __restrict__ ob)
{
    extern __shared__ float sm[];
    float* Qst  = sm;                    // [128][65]
    float* Kst  = Qst + 128 * 65;        // [128][65]
    float* Vs   = Kst + 128 * 65;        // [64][128]
    float* Ps   = Vs + 64 * 128;         // [64][65]
    float* rowM = Ps + 64 * 65;
    float* rowL = rowM + 64;
    float* rowC = rowL + 64;

    const int tid = threadIdx.x;
    const int qt  = blockIdx.x;
    const int h   = blockIdx.y;
    const int kvh = h >> 2;
    const int m0  = qt * 64;
    const float scale = 0.08838834764831845f;

    {
        const int lr = tid >> 5;
        const int d0 = (tid & 31) * 4;
#pragma unroll
        for (int p = 0; p < 8; p++) {
            int r = p * 8 + lr;
            float4 qv = *(const float4*)(qb + (size_t)(m0 + r) * HID_DIM + h * DH + d0);
            Qst[(d0 + 0) * 65 + r] = qv.x;
            Qst[(d0 + 1) * 65 + r] = qv.y;
            Qst[(d0 + 2) * 65 + r] = qv.z;
            Qst[(d0 + 3) * 65 + r] = qv.w;
        }
    }
    if (tid < 64) { rowM[tid] = -1e30f; rowL[tid] = 0.f; }

    const int trp = (tid >> 4) * 4;
    const int tcS = (tid & 15) * 4;
    const int tcP = (tid & 15) * 8;

    float acc[4][8];
#pragma unroll
    for (int i = 0; i < 4; i++)
#pragma unroll
        for (int j = 0; j < 8; j++) acc[i][j] = 0.f;

    for (int jt = 0; jt <= qt; jt++) {
        __syncthreads();

        {
            const int lr = tid >> 5;
            const int d0 = (tid & 31) * 4;
#pragma unroll
            for (int p = 0; p < 8; p++) {
                int r = p * 8 + lr;
                size_t base = (size_t)(jt * 64 + r) * KVW + kvh * DH + d0;
                float4 kv = *(const float4*)(kb + base);
                Kst[(d0 + 0) * 65 + r] = kv.x;
                Kst[(d0 + 1) * 65 + r] = kv.y;
                Kst[(d0 + 2) * 65 + r] = kv.z;
                Kst[(d0 + 3) * 65 + r] = kv.w;
                float4 vv = *(const float4*)(vb + base);
                *(float4*)&Vs[r * 128 + d0] = vv;
            }
        }
        __syncthreads();

        {
            float s[4][4];
#pragma unroll
            for (int i = 0; i < 4; i++)
#pragma unroll
                for (int j = 0; j < 4; j++) s[i][j] = 0.f;

            for (int d = 0; d < 128; d++) {
                const int base = d * 65;
                float qr[4], kr[4];
#pragma unroll
                for (int i = 0; i < 4; i++) qr[i] = Qst[base + trp + i];
#pragma unroll
                for (int j = 0; j < 4; j++) kr[j] = Kst[base + tcS + j];
#pragma unroll
                for (int i = 0; i < 4; i++)
#pragma unroll
                    for (int j = 0; j < 4; j++)
                        s[i][j] = fmaf(qr[i], kr[j], s[i][j]);
            }
#pragma unroll
            for (int i = 0; i < 4; i++) {
                int gm = m0 + trp + i;
#pragma unroll
                for (int j = 0; j < 4; j++) {
                    int gn = jt * 64 + tcS + j;
                    float v = s[i][j] * scale;
                    if (gn > gm) v = -1e30f;
                    Ps[(trp + i) * 65 + tcS + j] = v;
                }
            }
        }
        __syncthreads();

        {
            const int r = tid >> 2, sub = tid & 3;
            float* pr = &Ps[r * 65];
            float mx = -1e30f;
#pragma unroll
            for (int c = 0; c < 16; c++) mx = fmaxf(mx, pr[sub * 16 + c]);
            mx = fmaxf(mx, __shfl_xor_sync(0xFFFFFFFFu, mx, 1));
            mx = fmaxf(mx, __shfl_xor_sync(0xFFFFFFFFu, mx, 2));
            float mold = rowM[r];
            mx = fmaxf(mx, mold);
            float sum = 0.f;
#pragma unroll
            for (int c = 0; c < 16; c++) {
                float e = __expf(pr[sub * 16 + c] - mx);
                pr[sub * 16 + c] = e;
                sum += e;
            }
            sum += __shfl_xor_sync(0xFFFFFFFFu, sum, 1);
            sum += __shfl_xor_sync(0xFFFFFFFFu, sum, 2);
            if (sub == 0) {
                float corr = __expf(mold - mx);
                rowC[r] = corr;
                rowL[r] = rowL[r] * corr + sum;
                rowM[r] = mx;
            }
        }
        __syncthreads();

        {
            float cr[4];
#pragma unroll
            for (int i = 0; i < 4; i++) cr[i] = rowC[trp + i];
#pragma unroll
            for (int i = 0; i < 4; i++)
#pragma unroll
                for (int j = 0; j < 8; j++) acc[i][j] *= cr[i];

            for (int n = 0; n < 64; n++) {
                float p[4];
#pragma unroll
                for (int i = 0; i < 4; i++) p[i] = Ps[(trp + i) * 65 + n];
                float4 v0 = *(const float4*)&Vs[n * 128 + tcP];
                float4 v1 = *(const float4*)&Vs[n * 128 + tcP + 4];
#pragma unroll
                for (int i = 0; i < 4; i++) {
                    acc[i][0] = fmaf(p[i], v0.x, acc[i][0]);
                    acc[i][1] = fmaf(p[i], v0.y, acc[i][1]);
                    acc[i][2] = fmaf(p[i], v0.z, acc[i][2]);
                    acc[i][3] = fmaf(p[i], v0.w, acc[i][3]);
                    acc[i][4] = fmaf(p[i], v1.x, acc[i][4]);
                    acc[i][5] = fmaf(p[i], v1.y, acc[i][5]);
                    acc[i][6] = fmaf(p[i], v1.z, acc[i][6]);
                    acc[i][7] = fmaf(p[i], v1.w, acc[i][7]);
                }
            }
        }
    }

    float invl[4];
#pragma unroll
    for (int i = 0; i < 4; i++) invl[i] = 1.f / rowL[trp + i];
#pragma unroll
    for (int i = 0; i < 4; i++) {
        float* op = ob + (size_t)(m0 + trp + i) * HID_DIM + h * DH + tcP;
        float4 o0 = make_float4(acc[i][0] * invl[i], acc[i][1] * invl[i],
                                acc[i][2] * invl[i], acc[i][3] * invl[i]);
        float4 o1 = make_float4(acc[i][4] * invl[i], acc[i][5] * invl[i],
                                acc[i][6] * invl[i], acc[i][7] * invl[i]);
        *(float4*)(op + 0) = o0;
        *(float4*)(op + 4) = o1;
    }
}

// ---------------------------------------------------------------------------
// Orchestration
// ---------------------------------------------------------------------------
extern "C" void kernel_launch(void* const* d_in, const int* in_sizes, int n_in,
                              void* d_out, int out_size)
{
    const float* hidden = (const float*)d_in[0];
    const float* wq = (const float*)d_in[2];
    const float* wk = (const float*)d_in[3];
    const float* wv = (const float*)d_in[4];
    const float* wo = (const float*)d_in[5];
    float* out = (float*)d_out;

    float *qp, *kp, *vp, *ap;
    cudaGetSymbolAddress((void**)&qp, g_q);
    cudaGetSymbolAddress((void**)&kp, g_k);
    cudaGetSymbolAddress((void**)&vp, g_v);
    cudaGetSymbolAddress((void**)&ap, g_attn);
    __nv_bfloat16 *hh, *hl, *ath, *atl, *qth, *qtl, *kth, *ktl, *vth, *vtl, *oth, *otl;
    cudaGetSymbolAddress((void**)&hh, g_hid_hi);  cudaGetSymbolAddress((void**)&hl, g_hid_lo);
    cudaGetSymbolAddress((void**)&ath, g_at_hi);  cudaGetSymbolAddress((void**)&atl, g_at_lo);
    cudaGetSymbolAddress((void**)&qth, g_wqT_hi); cudaGetSymbolAddress((void**)&qtl, g_wqT_lo);
    cudaGetSymbolAddress((void**)&kth, g_wkT_hi); cudaGetSymbolAddress((void**)&ktl, g_wkT_lo);
    cudaGetSymbolAddress((void**)&vth, g_wvT_hi); cudaGetSymbolAddress((void**)&vtl, g_wvT_lo);
    cudaGetSymbolAddress((void**)&oth, g_woT_hi); cudaGetSymbolAddress((void**)&otl, g_woT_lo);

    cudaFuncSetAttribute(attn_kernel, cudaFuncAttributeMaxDynamicSharedMemorySize, ATT_SMEM_BYTES);
    cudaFuncSetAttribute(gemm_bf16x3_kernel, cudaFuncAttributeMaxDynamicSharedMemorySize, GSMEM_TOTAL);

    // Split + transpose
    conv_hilo_kernel<<<(S_LEN * HID_DIM) / 1024, 256>>>(hidden, hh, hl, S_LEN * HID_DIM);
    dim3 tb(32, 8);
    conv_t_kernel<<<dim3(HID_DIM / 32, HID_DIM / 32), tb>>>(wq, qth, qtl, HID_DIM, HID_DIM);
    conv_t_kernel<<<dim3(KVW / 32, HID_DIM / 32), tb>>>(wk, kth, ktl, HID_DIM, KVW);
    conv_t_kernel<<<dim3(KVW / 32, HID_DIM / 32), tb>>>(wv, vth, vtl, HID_DIM, KVW);
    conv_t_kernel<<<dim3(HID_DIM / 32, HID_DIM / 32), tb>>>(wo, oth, otl, HID_DIM, HID_DIM);

    // Projections on HMMA (bf16x3 via wmma)
    gemm_bf16x3_kernel<<<dim3(HID_DIM / 128, S_LEN / 128), 256, GSMEM_TOTAL>>>(
        hh, hl, qth, qtl, qp, S_LEN, HID_DIM, HID_DIM);
    gemm_bf16x3_kernel<<<dim3(KVW / 128, S_LEN / 128), 256, GSMEM_TOTAL>>>(
        hh, hl, kth, ktl, kp, S_LEN, KVW, HID_DIM);
    gemm_bf16x3_kernel<<<dim3(KVW / 128, S_LEN / 128), 256, GSMEM_TOTAL>>>(
        hh, hl, vth, vtl, vp, S_LEN, KVW, HID_DIM);

    // Attention
    attn_kernel<<<dim3(S_LEN / 64, NH), 256, ATT_SMEM_BYTES>>>(qp, kp, vp, ap);

    // Output projection
    conv_hilo_kernel<<<(S_LEN * HID_DIM) / 1024, 256>>>(ap, ath, atl, S_LEN * HID_DIM);
    gemm_bf16x3_kernel<<<dim3(HID_DIM / 128, S_LEN / 128), 256, GSMEM_TOTAL>>>(
        ath, atl, oth, otl, out, S_LEN, HID_DIM, HID_DIM);
}

// round 4
// speedup vs baseline: 4.0323x; 1.4015x over previous
#include <cuda_runtime.h>
#include <cuda_bf16.h>
#include <mma.h>
#include <cstdint>
#include <math.h>

using namespace nvcuda;

#define S_LEN 2048
#define HID_DIM 4096
#define NH 32
#define NKV 8
#define DH 128
#define KVW (NKV * DH)   // 1024

// ---------------------------------------------------------------------------
// Scratch (device globals: allocation-free)
// ---------------------------------------------------------------------------
__device__ float g_q[S_LEN * HID_DIM];
__device__ float g_k[S_LEN * KVW];
__device__ float g_v[S_LEN * KVW];
__device__ float g_attn[S_LEN * HID_DIM];

__device__ __nv_bfloat16 g_hid_hi[S_LEN * HID_DIM];
__device__ __nv_bfloat16 g_hid_lo[S_LEN * HID_DIM];
__device__ __nv_bfloat16 g_at_hi[S_LEN * HID_DIM];
__device__ __nv_bfloat16 g_at_lo[S_LEN * HID_DIM];
__device__ __nv_bfloat16 g_q_hi[S_LEN * HID_DIM];
__device__ __nv_bfloat16 g_q_lo[S_LEN * HID_DIM];
__device__ __nv_bfloat16 g_k_hi[S_LEN * KVW];
__device__ __nv_bfloat16 g_k_lo[S_LEN * KVW];
__device__ __nv_bfloat16 g_v_hi[S_LEN * KVW];
__device__ __nv_bfloat16 g_v_lo[S_LEN * KVW];
__device__ __nv_bfloat16 g_wqT_hi[HID_DIM * HID_DIM];
__device__ __nv_bfloat16 g_wqT_lo[HID_DIM * HID_DIM];
__device__ __nv_bfloat16 g_wkT_hi[KVW * HID_DIM];
__device__ __nv_bfloat16 g_wkT_lo[KVW * HID_DIM];
__device__ __nv_bfloat16 g_wvT_hi[KVW * HID_DIM];
__device__ __nv_bfloat16 g_wvT_lo[KVW * HID_DIM];
__device__ __nv_bfloat16 g_woT_hi[HID_DIM * HID_DIM];
__device__ __nv_bfloat16 g_woT_lo[HID_DIM * HID_DIM];

// ---------------------------------------------------------------------------
// PTX helpers (all baseline sm_80 PTX — safe on compute_103)
// ---------------------------------------------------------------------------
__device__ __forceinline__ uint32_t smem_u32(const void* p) {
    return (uint32_t)__cvta_generic_to_shared(p);
}
#define CP_ASYNC16(sa, gp) \
    asm volatile("cp.async.cg.shared.global [%0], [%1], 16;" :: "r"(sa), "l"(gp))
#define CP_COMMIT() asm volatile("cp.async.commit_group;" ::: "memory")
#define CP_WAIT(n)  asm volatile("cp.async.wait_group %0;" :: "n"(n) : "memory")

#define LDSM_X4(r0, r1, r2, r3, a) \
    asm volatile("ldmatrix.sync.aligned.m8n8.x4.shared.b16 {%0,%1,%2,%3},[%4];" \
        : "=r"(r0), "=r"(r1), "=r"(r2), "=r"(r3) : "r"(a))
#define LDSM_X2(r0, r1, a) \
    asm volatile("ldmatrix.sync.aligned.m8n8.x2.shared.b16 {%0,%1},[%2];" \
        : "=r"(r0), "=r"(r1) : "r"(a))
#define LDSM_X2T(r0, r1, a) \
    asm volatile("ldmatrix.sync.aligned.m8n8.x2.trans.shared.b16 {%0,%1},[%2];" \
        : "=r"(r0), "=r"(r1) : "r"(a))
#define MMA16816(d, a0, a1, a2, a3, b0, b1) \
    asm volatile("mma.sync.aligned.m16n8k16.row.col.f32.bf16.bf16.f32 " \
        "{%0,%1,%2,%3},{%4,%5,%6,%7},{%8,%9},{%0,%1,%2,%3};" \
        : "+f"((d)[0]), "+f"((d)[1]), "+f"((d)[2]), "+f"((d)[3]) \
        : "r"(a0), "r"(a1), "r"(a2), "r"(a3), "r"(b0), "r"(b1))

// ---------------------------------------------------------------------------
// Split fp32 -> (hi, lo) bf16, elementwise
// ---------------------------------------------------------------------------
__global__ void conv_hilo_kernel(const float* __restrict__ x,
                                 __nv_bfloat16* __restrict__ hi,
                                 __nv_bfloat16* __restrict__ lo, int n)
{
    int i = (blockIdx.x * blockDim.x + threadIdx.x) * 4;
    if (i >= n) return;
    float4 v = *(const float4*)(x + i);
    __nv_bfloat16 h0 = __float2bfloat16_rn(v.x);
    __nv_bfloat16 h1 = __float2bfloat16_rn(v.y);
    __nv_bfloat16 h2 = __float2bfloat16_rn(v.z);
    __nv_bfloat16 h3 = __float2bfloat16_rn(v.w);
    __nv_bfloat16 l0 = __float2bfloat16_rn(v.x - __bfloat162float(h0));
    __nv_bfloat16 l1 = __float2bfloat16_rn(v.y - __bfloat162float(h1));
    __nv_bfloat16 l2 = __float2bfloat16_rn(v.z - __bfloat162float(h2));
    __nv_bfloat16 l3 = __float2bfloat16_rn(v.w - __bfloat162float(h3));
    __nv_bfloat162* hp = (__nv_bfloat162*)(hi + i);
    __nv_bfloat162* lp = (__nv_bfloat162*)(lo + i);
    hp[0] = __nv_bfloat162(h0, h1); hp[1] = __nv_bfloat162(h2, h3);
    lp[0] = __nv_bfloat162(l0, l1); lp[1] = __nv_bfloat162(l2, l3);
}

// ---------------------------------------------------------------------------
// Transpose + split: B[K,N] fp32 -> Thi/Tlo[N,K] bf16
// ---------------------------------------------------------------------------
__global__ void conv_t_kernel(const float* __restrict__ B,
                              __nv_bfloat16* __restrict__ Thi,
                              __nv_bfloat16* __restrict__ Tlo, int K, int N)
{
    __shared__ float t[32][33];
    const int n0 = blockIdx.x * 32, k0 = blockIdx.y * 32;
    const int tx = threadIdx.x, ty = threadIdx.y;
#pragma unroll
    for (int i = 0; i < 32; i += 8)
        t[ty + i][tx] = B[(size_t)(k0 + ty + i) * N + n0 + tx];
    __syncthreads();
#pragma unroll
    for (int i = 0; i < 32; i += 8) {
        float v = t[tx][ty + i];
        __nv_bfloat16 h = __float2bfloat16_rn(v);
        size_t o = (size_t)(n0 + ty + i) * K + k0 + tx;
        Thi[o] = h;
        Tlo[o] = __float2bfloat16_rn(v - __bfloat162float(h));
    }
}

// ---------------------------------------------------------------------------
// bf16x3 wmma (HMMA) GEMM (unchanged from R3)
// ---------------------------------------------------------------------------
#define GLD 40
#define GMAT (128 * GLD * 2)
#define GSTAGE (4 * GMAT)
#define GSMEM_TOTAL (2 * GSTAGE)

__global__ void __launch_bounds__(256) gemm_bf16x3_kernel(
    const __nv_bfloat16* __restrict__ Ahi, const __nv_bfloat16* __restrict__ Alo,
    const __nv_bfloat16* __restrict__ Bhi, const __nv_bfloat16* __restrict__ Blo,
    float* __restrict__ C, int M, int N, int K)
{
    extern __shared__ char smem[];
    const int tid = threadIdx.x;
    const int wid = tid >> 5;
    const int wm = wid >> 2;
    const int wn = wid & 3;
    const int m0 = blockIdx.y * 128;
    const int n0 = blockIdx.x * 128;
    const int lr = tid >> 2;
    const int cs = (tid & 3) * 8;
    const uint32_t sbase = smem_u32(smem);

    auto issue = [&](int it, int s) {
        const int k0 = it * 32;
        const uint32_t st = sbase + s * GSTAGE;
#pragma unroll
        for (int p = 0; p < 2; p++) {
            int row = lr + p * 64;
            uint32_t so = (uint32_t)((row * GLD + cs) * 2);
            size_t gA = (size_t)(m0 + row) * K + k0 + cs;
            size_t gB = (size_t)(n0 + row) * K + k0 + cs;
            CP_ASYNC16(st + 0 * GMAT + so, (const void*)(Ahi + gA));
            CP_ASYNC16(st + 1 * GMAT + so, (const void*)(Alo + gA));
            CP_ASYNC16(st + 2 * GMAT + so, (const void*)(Bhi + gB));
            CP_ASYNC16(st + 3 * GMAT + so, (const void*)(Blo + gB));
        }
        CP_COMMIT();
    };

    wmma::fragment<wmma::accumulator, 16, 16, 16, float> acc[4][2];
#pragma unroll
    for (int i = 0; i < 4; i++)
#pragma unroll
        for (int j = 0; j < 2; j++) wmma::fill_fragment(acc[i][j], 0.f);

    const int nIter = K >> 5;
    issue(0, 0);

    for (int it = 0; it < nIter; ++it) {
        if (it + 1 < nIter) { issue(it + 1, (it + 1) & 1); CP_WAIT(1); }
        else { CP_WAIT(0); }
        __syncthreads();

        const __nv_bfloat16* stg = (const __nv_bfloat16*)(smem + (it & 1) * GSTAGE);
        const __nv_bfloat16* As_h = stg;
        const __nv_bfloat16* As_l = stg + 128 * GLD;
        const __nv_bfloat16* Bs_h = stg + 2 * 128 * GLD;
        const __nv_bfloat16* Bs_l = stg + 3 * 128 * GLD;

#pragma unroll
        for (int ks = 0; ks < 2; ks++) {
            wmma::fragment<wmma::matrix_a, 16, 16, 16, __nv_bfloat16, wmma::row_major> ah[4], al[4];
            wmma::fragment<wmma::matrix_b, 16, 16, 16, __nv_bfloat16, wmma::col_major> bh[2], bl[2];
#pragma unroll
            for (int i = 0; i < 4; i++) {
                const int r = (wm * 64 + i * 16) * GLD + ks * 16;
                wmma::load_matrix_sync(ah[i], As_h + r, GLD);
                wmma::load_matrix_sync(al[i], As_l + r, GLD);
            }
#pragma unroll
            for (int j = 0; j < 2; j++) {
                const int r = (wn * 32 + j * 16) * GLD + ks * 16;
                wmma::load_matrix_sync(bh[j], Bs_h + r, GLD);
                wmma::load_matrix_sync(bl[j], Bs_l + r, GLD);
            }
#pragma unroll
            for (int i = 0; i < 4; i++)
#pragma unroll
                for (int j = 0; j < 2; j++) {
                    wmma::mma_sync(acc[i][j], ah[i], bh[j], acc[i][j]);
                    wmma::mma_sync(acc[i][j], ah[i], bl[j], acc[i][j]);
                    wmma::mma_sync(acc[i][j], al[i], bh[j], acc[i][j]);
                }
        }
        __syncthreads();
    }

#pragma unroll
    for (int i = 0; i < 4; i++)
#pragma unroll
        for (int j = 0; j < 2; j++) {
            float* cp = C + (size_t)(m0 + wm * 64 + i * 16) * N + n0 + wn * 32 + j * 16;
            wmma::store_matrix_sync(cp, acc[i][j], N, wmma::mem_row_major);
        }
}

// ---------------------------------------------------------------------------
// Tensor-core flash attention: mma.m16n8k16 bf16x3 for QK^T and PV,
// fp32 online softmax, cp.async double-buffered K/V tiles, causal, GQA.
// Block = (64 queries, head). 256 threads = 8 warps (4 m-slices x 2 n-slices).
// ---------------------------------------------------------------------------
#define LDQ 136            // bf16 elements per smem row (Q/K/V), 272B stride
#define LDSF 76            // fp32 S row stride (conflict-free)
#define LDP 72             // bf16 P row stride (mult of 8 for ldmatrix)
#define AOFF_QH 0
#define AOFF_QL 17408
#define AKV_BASE 34816
#define AKV_STAGE 69632    // Kh,Kl,Vh,Vl per stage (4 x 17408)
#define AOFF_S  174080
#define AOFF_PH 193536
#define AOFF_PL 202752
#define AOFF_RM 211968
#define AOFF_RL 212224
#define AOFF_RC 212480
#define ATT_SMEM 212736

__global__ void __launch_bounds__(256, 1) attn_mma_kernel(
    const __nv_bfloat16* __restrict__ Qh, const __nv_bfloat16* __restrict__ Ql,
    const __nv_bfloat16* __restrict__ Kh, const __nv_bfloat16* __restrict__ Kl,
    const __nv_bfloat16* __restrict__ Vh, const __nv_bfloat16* __restrict__ Vl,
    float* __restrict__ ob)
{
    extern __shared__ char sm[];
    const uint32_t sb = smem_u32(sm);
    float* rowM = (float*)(sm + AOFF_RM);
    float* rowL = (float*)(sm + AOFF_RL);
    float* rowC = (float*)(sm + AOFF_RC);

    const int tid = threadIdx.x;
    const int wid = tid >> 5, lane = tid & 31;
    const int wm = wid & 3;        // 16-row m slice
    const int wn = wid >> 2;       // 0..1
    const int qt = 31 - (int)blockIdx.x;   // heavy tiles first
    const int h = blockIdx.y;
    const int kvh = h >> 2;
    const int m0 = qt * 64;
    const float scale = 0.08838834764831845f;

    // K/V tile prefetch into stage s (cp.async, one commit group)
    auto kv_issue = [&](int jt, int s) {
        const uint32_t st = sb + AKV_BASE + s * AKV_STAGE;
#pragma unroll
        for (int i = 0; i < 4; i++) {
            int idx = tid + i * 256;          // 0..1023
            int row = idx >> 4, seg = idx & 15;
            uint32_t so = (uint32_t)((row * LDQ + seg * 8) * 2);
            size_t g = (size_t)(jt * 64 + row) * KVW + kvh * DH + seg * 8;
            CP_ASYNC16(st + 0 * 17408 + so, (const void*)(Kh + g));
            CP_ASYNC16(st + 1 * 17408 + so, (const void*)(Kl + g));
            CP_ASYNC16(st + 2 * 17408 + so, (const void*)(Vh + g));
            CP_ASYNC16(st + 3 * 17408 + so, (const void*)(Vl + g));
        }
        CP_COMMIT();
    };

    kv_issue(0, 0);

    // Load Q tile (hi/lo) to smem
    {
        __nv_bfloat16* qh_s = (__nv_bfloat16*)(sm + AOFF_QH);
        __nv_bfloat16* ql_s = (__nv_bfloat16*)(sm + AOFF_QL);
#pragma unroll
        for (int i = 0; i < 4; i++) {
            int idx = tid + i * 256;
            int row = idx >> 4, seg = idx & 15;
            size_t g = (size_t)(m0 + row) * HID_DIM + h * DH + seg * 8;
            *(uint4*)(qh_s + row * LDQ + seg * 8) = *(const uint4*)(Qh + g);
            *(uint4*)(ql_s + row * LDQ + seg * 8) = *(const uint4*)(Ql + g);
        }
    }
    if (tid < 64) { rowM[tid] = -1e30f; rowL[tid] = 0.f; }

    // O accumulators: warp tile 16 rows x 64 cols = 8 n-frags
    float o[8][4];
#pragma unroll
    for (int j = 0; j < 8; j++)
#pragma unroll
        for (int r = 0; r < 4; r++) o[j][r] = 0.f;

    const int r0l = lane >> 2;            // 0..7
    const int c0l = (lane & 3) * 2;

    for (int jt = 0; jt <= qt; jt++) {
        const int s = jt & 1;
        CP_WAIT(0);
        __syncthreads();
        if (jt < qt) kv_issue(jt + 1, s ^ 1);

        const uint32_t kh_b = sb + AKV_BASE + s * AKV_STAGE;
        const uint32_t kl_b = kh_b + 17408;
        const uint32_t vh_b = kh_b + 2 * 17408;
        const uint32_t vl_b = kh_b + 3 * 17408;
        const uint32_t qh_b = sb + AOFF_QH, ql_b = sb + AOFF_QL;

        // ---- S = Q K^T (bf16x3) ----
        {
            float sf[4][4];
#pragma unroll
            for (int j = 0; j < 4; j++)
#pragma unroll
                for (int r = 0; r < 4; r++) sf[j][r] = 0.f;

            const int ar = wm * 16 + (lane & 15);
#pragma unroll
            for (int k0 = 0; k0 < 128; k0 += 16) {
                const uint32_t aoff = (uint32_t)((ar * LDQ + k0 + (lane >> 4) * 8) * 2);
                uint32_t ah[4], al[4];
                LDSM_X4(ah[0], ah[1], ah[2], ah[3], qh_b + aoff);
                LDSM_X4(al[0], al[1], al[2], al[3], ql_b + aoff);
#pragma unroll
                for (int j = 0; j < 4; j++) {
                    const int bn = wn * 32 + j * 8 + (lane & 7);
                    const uint32_t boff =
                        (uint32_t)((bn * LDQ + k0 + ((lane & 8) ? 8 : 0)) * 2);
                    uint32_t bh[2], bl[2];
                    LDSM_X2(bh[0], bh[1], kh_b + boff);
                    LDSM_X2(bl[0], bl[1], kl_b + boff);
                    MMA16816(sf[j], ah[0], ah[1], ah[2], ah[3], bh[0], bh[1]);
                    MMA16816(sf[j], ah[0], ah[1], ah[2], ah[3], bl[0], bl[1]);
                    MMA16816(sf[j], al[0], al[1], al[2], al[3], bh[0], bh[1]);
                }
            }
            // store S tile
            float* S_s = (float*)(sm + AOFF_S);
            const int sr0 = wm * 16 + r0l;
#pragma unroll
            for (int j = 0; j < 4; j++) {
                const int c = wn * 32 + j * 8 + c0l;
                S_s[sr0 * LDSF + c] = sf[j][0];
                S_s[sr0 * LDSF + c + 1] = sf[j][1];
                S_s[(sr0 + 8) * LDSF + c] = sf[j][2];
                S_s[(sr0 + 8) * LDSF + c + 1] = sf[j][3];
            }
        }
        __syncthreads();

        // ---- online softmax (4 threads/row), write P hi/lo ----
        {
            const int r = tid >> 2, sub = tid & 3;
            float* S_s = (float*)(sm + AOFF_S);
            __nv_bfloat16* ph_s = (__nv_bfloat16*)(sm + AOFF_PH);
            __nv_bfloat16* pl_s = (__nv_bfloat16*)(sm + AOFF_PL);
            const int gr = m0 + r, jn0 = jt * 64;
            float st[16];
            float mx = -1e30f;
#pragma unroll
            for (int c = 0; c < 16; c++) {
                int cc = sub * 16 + c;
                float v = S_s[r * LDSF + cc] * scale;
                if (jn0 + cc > gr) v = -1e30f;
                st[c] = v;
                mx = fmaxf(mx, v);
            }
            mx = fmaxf(mx, __shfl_xor_sync(0xFFFFFFFFu, mx, 1));
            mx = fmaxf(mx, __shfl_xor_sync(0xFFFFFFFFu, mx, 2));
            float mold = rowM[r];
            mx = fmaxf(mx, mold);
            float sum = 0.f;
#pragma unroll
            for (int c = 0; c < 16; c++) {
                float e = __expf(st[c] - mx);
                sum += e;
                __nv_bfloat16 hp = __float2bfloat16_rn(e);
                ph_s[r * LDP + sub * 16 + c] = hp;
                pl_s[r * LDP + sub * 16 + c] =
                    __float2bfloat16_rn(e - __bfloat162float(hp));
            }
            sum += __shfl_xor_sync(0xFFFFFFFFu, sum, 1);
            sum += __shfl_xor_sync(0xFFFFFFFFu, sum, 2);
            if (sub == 0) {
                float corr = __expf(mold - mx);
                rowC[r] = corr;
                rowL[r] = rowL[r] * corr + sum;
                rowM[r] = mx;
            }
        }
        __syncthreads();

        // ---- O = O*corr + P V (bf16x3) ----
        {
            const float cr0 = rowC[wm * 16 + r0l];
            const float cr1 = rowC[wm * 16 + r0l + 8];
#pragma unroll
            for (int j = 0; j < 8; j++) {
                o[j][0] *= cr0; o[j][1] *= cr0;
                o[j][2] *= cr1; o[j][3] *= cr1;
            }
            const uint32_t ph_b = sb + AOFF_PH, pl_b = sb + AOFF_PL;
            const int ar = wm * 16 + (lane & 15);
#pragma unroll
            for (int k0 = 0; k0 < 64; k0 += 16) {
                const uint32_t aoff = (uint32_t)((ar * LDP + k0 + (lane >> 4) * 8) * 2);
                uint32_t ph[4], pl[4];
                LDSM_X4(ph[0], ph[1], ph[2], ph[3], ph_b + aoff);
                LDSM_X4(pl[0], pl[1], pl[2], pl[3], pl_b + aoff);
                const int vk = k0 + (lane & 15);
#pragma unroll
                for (int j = 0; j < 8; j++) {
                    const int d0 = wn * 64 + j * 8;
                    const uint32_t boff = (uint32_t)((vk * LDQ + d0) * 2);
                    uint32_t vh[2], vl[2];
                    LDSM_X2T(vh[0], vh[1], vh_b + boff);
                    LDSM_X2T(vl[0], vl[1], vl_b + boff);
                    MMA16816(o[j], ph[0], ph[1], ph[2], ph[3], vh[0], vh[1]);
                    MMA16816(o[j], pl[0], pl[1], pl[2], pl[3], vh[0], vh[1]);
                    MMA16816(o[j], ph[0], ph[1], ph[2], ph[3], vl[0], vl[1]);
                }
            }
        }
    }

    // normalize + store
    {
        const int gr0 = m0 + wm * 16 + r0l;
        const float il0 = 1.f / rowL[wm * 16 + r0l];
        const float il1 = 1.f / rowL[wm * 16 + r0l + 8];
#pragma unroll
        for (int j = 0; j < 8; j++) {
            const int d = h * DH + wn * 64 + j * 8 + c0l;
            float2 v0 = make_float2(o[j][0] * il0, o[j][1] * il0);
            float2 v1 = make_float2(o[j][2] * il1, o[j][3] * il1);
            *(float2*)(ob + (size_t)gr0 * HID_DIM + d) = v0;
            *(float2*)(ob + (size_t)(gr0 + 8) * HID_DIM + d) = v1;
        }
    }
}

// ---------------------------------------------------------------------------
// Orchestration
// ---------------------------------------------------------------------------
extern "C" void kernel_launch(void* const* d_in, const int* in_sizes, int n_in,
                              void* d_out, int out_size)
{
    const float* hidden = (const float*)d_in[0];
    const float* wq = (const float*)d_in[2];
    const float* wk = (const float*)d_in[3];
    const float* wv = (const float*)d_in[4];
    const float* wo = (const float*)d_in[5];
    float* out = (float*)d_out;

    float *qp, *kp, *vp, *ap;
    cudaGetSymbolAddress((void**)&qp, g_q);
    cudaGetSymbolAddress((void**)&kp, g_k);
    cudaGetSymbolAddress((void**)&vp, g_v);
    cudaGetSymbolAddress((void**)&ap, g_attn);
    __nv_bfloat16 *hh, *hl, *ath, *atl, *qhh, *qhl, *khh, *khl, *vhh, *vhl;
    __nv_bfloat16 *qth, *qtl, *kth, *ktl, *vth, *vtl, *oth, *otl;
    cudaGetSymbolAddress((void**)&hh, g_hid_hi);  cudaGetSymbolAddress((void**)&hl, g_hid_lo);
    cudaGetSymbolAddress((void**)&ath, g_at_hi);  cudaGetSymbolAddress((void**)&atl, g_at_lo);
    cudaGetSymbolAddress((void**)&qhh, g_q_hi);   cudaGetSymbolAddress((void**)&qhl, g_q_lo);
    cudaGetSymbolAddress((void**)&khh, g_k_hi);   cudaGetSymbolAddress((void**)&khl, g_k_lo);
    cudaGetSymbolAddress((void**)&vhh, g_v_hi);   cudaGetSymbolAddress((void**)&vhl, g_v_lo);
    cudaGetSymbolAddress((void**)&qth, g_wqT_hi); cudaGetSymbolAddress((void**)&qtl, g_wqT_lo);
    cudaGetSymbolAddress((void**)&kth, g_wkT_hi); cudaGetSymbolAddress((void**)&ktl, g_wkT_lo);
    cudaGetSymbolAddress((void**)&vth, g_wvT_hi); cudaGetSymbolAddress((void**)&vtl, g_wvT_lo);
    cudaGetSymbolAddress((void**)&oth, g_woT_hi); cudaGetSymbolAddress((void**)&otl, g_woT_lo);

    cudaFuncSetAttribute(attn_mma_kernel, cudaFuncAttributeMaxDynamicSharedMemorySize, ATT_SMEM);
    cudaFuncSetAttribute(gemm_bf16x3_kernel, cudaFuncAttributeMaxDynamicSharedMemorySize, GSMEM_TOTAL);

    // Split + transpose
    conv_hilo_kernel<<<(S_LEN * HID_DIM) / 1024, 256>>>(hidden, hh, hl, S_LEN * HID_DIM);
    dim3 tb(32, 8);
    conv_t_kernel<<<dim3(HID_DIM / 32, HID_DIM / 32), tb>>>(wq, qth, qtl, HID_DIM, HID_DIM);
    conv_t_kernel<<<dim3(KVW / 32, HID_DIM / 32), tb>>>(wk, kth, ktl, HID_DIM, KVW);
    conv_t_kernel<<<dim3(KVW / 32, HID_DIM / 32), tb>>>(wv, vth, vtl, HID_DIM, KVW);
    conv_t_kernel<<<dim3(HID_DIM / 32, HID_DIM / 32), tb>>>(wo, oth, otl, HID_DIM, HID_DIM);

    // Projections (HMMA bf16x3)
    gemm_bf16x3_kernel<<<dim3(HID_DIM / 128, S_LEN / 128), 256, GSMEM_TOTAL>>>(
        hh, hl, qth, qtl, qp, S_LEN, HID_DIM, HID_DIM);
    gemm_bf16x3_kernel<<<dim3(KVW / 128, S_LEN / 128), 256, GSMEM_TOTAL>>>(
        hh, hl, kth, ktl, kp, S_LEN, KVW, HID_DIM);
    gemm_bf16x3_kernel<<<dim3(KVW / 128, S_LEN / 128), 256, GSMEM_TOTAL>>>(
        hh, hl, vth, vtl, vp, S_LEN, KVW, HID_DIM);

    // Split Q/K/V to bf16 hi/lo for the tensor-core attention
    conv_hilo_kernel<<<(S_LEN * HID_DIM) / 1024, 256>>>(qp, qhh, qhl, S_LEN * HID_DIM);
    conv_hilo_kernel<<<(S_LEN * KVW) / 1024, 256>>>(kp, khh, khl, S_LEN * KVW);
    conv_hilo_kernel<<<(S_LEN * KVW) / 1024, 256>>>(vp, vhh, vhl, S_LEN * KVW);

    // Attention (tensor cores)
    attn_mma_kernel<<<dim3(S_LEN / 64, NH), 256, ATT_SMEM>>>(
        qhh, qhl, khh, khl, vhh, vhl, ap);

    // Output projection
    conv_hilo_kernel<<<(S_LEN * HID_DIM) / 1024, 256>>>(ap, ath, atl, S_LEN * HID_DIM);
    gemm_bf16x3_kernel<<<dim3(HID_DIM / 128, S_LEN / 128), 256, GSMEM_TOTAL>>>(
        ath, atl, oth, otl, out, S_LEN, HID_DIM, HID_DIM);
}

// round 6
// speedup vs baseline: 4.8924x; 1.2133x over previous
#include <cuda_runtime.h>
#include <cuda_bf16.h>
#include <cstdint>
#include <math.h>

#define S_LEN 2048
#define HID_DIM 4096
#define NH 32
#define NKV 8
#define DH 128
#define KVW (NKV * DH)     // 1024
#define QKVW 6144          // fused Q(4096) + K(1024) + V(1024) width

// ---------------------------------------------------------------------------
// Scratch (device globals: allocation-free)
// ---------------------------------------------------------------------------
__device__ __nv_bfloat16 g_hid_hi[S_LEN * HID_DIM];
__device__ __nv_bfloat16 g_hid_lo[S_LEN * HID_DIM];
__device__ __nv_bfloat16 g_qkv_hi[S_LEN * QKVW];
__device__ __nv_bfloat16 g_qkv_lo[S_LEN * QKVW];
__device__ __nv_bfloat16 g_at_hi[S_LEN * HID_DIM];
__device__ __nv_bfloat16 g_at_lo[S_LEN * HID_DIM];
__device__ __nv_bfloat16 g_wqkvT_hi[QKVW * HID_DIM];
__device__ __nv_bfloat16 g_wqkvT_lo[QKVW * HID_DIM];
__device__ __nv_bfloat16 g_woT_hi[HID_DIM * HID_DIM];
__device__ __nv_bfloat16 g_woT_lo[HID_DIM * HID_DIM];

// ---------------------------------------------------------------------------
// PTX helpers (baseline sm_80 PTX — safe on compute_103)
// ---------------------------------------------------------------------------
__device__ __forceinline__ uint32_t smem_u32(const void* p) {
    return (uint32_t)__cvta_generic_to_shared(p);
}
#define CP_ASYNC16(sa, gp) \
    asm volatile("cp.async.cg.shared.global [%0], [%1], 16;" :: "r"(sa), "l"(gp))
#define CP_COMMIT() asm volatile("cp.async.commit_group;" ::: "memory")
#define CP_WAIT(n)  asm volatile("cp.async.wait_group %0;" :: "n"(n) : "memory")

#define LDSM_X4(r0, r1, r2, r3, a) \
    asm volatile("ldmatrix.sync.aligned.m8n8.x4.shared.b16 {%0,%1,%2,%3},[%4];" \
        : "=r"(r0), "=r"(r1), "=r"(r2), "=r"(r3) : "r"(a))
#define LDSM_X2(r0, r1, a) \
    asm volatile("ldmatrix.sync.aligned.m8n8.x2.shared.b16 {%0,%1},[%2];" \
        : "=r"(r0), "=r"(r1) : "r"(a))
#define LDSM_X2T(r0, r1, a) \
    asm volatile("ldmatrix.sync.aligned.m8n8.x2.trans.shared.b16 {%0,%1},[%2];" \
        : "=r"(r0), "=r"(r1) : "r"(a))
#define MMA16816(d, a0, a1, a2, a3, b0, b1) \
    asm volatile("mma.sync.aligned.m16n8k16.row.col.f32.bf16.bf16.f32 " \
        "{%0,%1,%2,%3},{%4,%5,%6,%7},{%8,%9},{%0,%1,%2,%3};" \
        : "+f"((d)[0]), "+f"((d)[1]), "+f"((d)[2]), "+f"((d)[3]) \
        : "r"(a0), "r"(a1), "r"(a2), "r"(a3), "r"(b0), "r"(b1))

// ---------------------------------------------------------------------------
// Split fp32 -> (hi, lo) bf16, elementwise
// ---------------------------------------------------------------------------
__global__ void conv_hilo_kernel(const float* __restrict__ x,
                                 __nv_bfloat16* __restrict__ hi,
                                 __nv_bfloat16* __restrict__ lo, int n)
{
    int i = (blockIdx.x * blockDim.x + threadIdx.x) * 4;
    if (i >= n) return;
    float4 v = *(const float4*)(x + i);
    __nv_bfloat16 h0 = __float2bfloat16_rn(v.x);
    __nv_bfloat16 h1 = __float2bfloat16_rn(v.y);
    __nv_bfloat16 h2 = __float2bfloat16_rn(v.z);
    __nv_bfloat16 h3 = __float2bfloat16_rn(v.w);
    __nv_bfloat16 l0 = __float2bfloat16_rn(v.x - __bfloat162float(h0));
    __nv_bfloat16 l1 = __float2bfloat16_rn(v.y - __bfloat162float(h1));
    __nv_bfloat16 l2 = __float2bfloat16_rn(v.z - __bfloat162float(h2));
    __nv_bfloat16 l3 = __float2bfloat16_rn(v.w - __bfloat162float(h3));
    __nv_bfloat162* hp = (__nv_bfloat162*)(hi + i);
    __nv_bfloat162* lp = (__nv_bfloat162*)(lo + i);
    hp[0] = __nv_bfloat162(h0, h1); hp[1] = __nv_bfloat162(h2, h3);
    lp[0] = __nv_bfloat162(l0, l1); lp[1] = __nv_bfloat162(l2, l3);
}

// ---------------------------------------------------------------------------
// Transpose + split: B[K,N] fp32 -> Thi/Tlo[N,K] bf16
// ---------------------------------------------------------------------------
__global__ void conv_t_kernel(const float* __restrict__ B,
                              __nv_bfloat16* __restrict__ Thi,
                              __nv_bfloat16* __restrict__ Tlo, int K, int N)
{
    __shared__ float t[32][33];
    const int n0 = blockIdx.x * 32, k0 = blockIdx.y * 32;
    const int tx = threadIdx.x, ty = threadIdx.y;
#pragma unroll
    for (int i = 0; i < 32; i += 8)
        t[ty + i][tx] = B[(size_t)(k0 + ty + i) * N + n0 + tx];
    __syncthreads();
#pragma unroll
    for (int i = 0; i < 32; i += 8) {
        float v = t[tx][ty + i];
        __nv_bfloat16 h = __float2bfloat16_rn(v);
        size_t o = (size_t)(n0 + ty + i) * K + k0 + tx;
        Thi[o] = h;
        Tlo[o] = __float2bfloat16_rn(v - __bfloat162float(h));
    }
}

// ---------------------------------------------------------------------------
// bf16x3 raw-mma GEMM: C[M,N] = A[M,K] @ B[K,N], B given transposed [N,K].
// CTA tile 256x128, 8 warps (warp tile 64x64), k32 stages, 3-stage cp.async.
// Epilogue: fp32 C, or bf16 (hi,lo) split.
// ---------------------------------------------------------------------------
#define TLD 40
#define SA_BYTES (256 * TLD * 2)              // 20480
#define SB_BYTES (128 * TLD * 2)              // 10240
#define STG_BYTES (2 * SA_BYTES + 2 * SB_BYTES)  // 61440
#define GEMM_SMEM (3 * STG_BYTES)             // 184320

__global__ void __launch_bounds__(256, 1) gemm_bf16x3_kernel(
    const __nv_bfloat16* __restrict__ Ahi, const __nv_bfloat16* __restrict__ Alo,
    const __nv_bfloat16* __restrict__ Bhi, const __nv_bfloat16* __restrict__ Blo,
    float* __restrict__ Cf,
    __nv_bfloat16* __restrict__ Chi, __nv_bfloat16* __restrict__ Clo,
    int M, int N, int K)
{
    extern __shared__ char smem[];
    const uint32_t sb = smem_u32(smem);
    const int tid = threadIdx.x;
    const int lane = tid & 31, wid = tid >> 5;
    const int wm = wid & 3, wn = wid >> 2;
    const int m0 = blockIdx.y * 256, n0 = blockIdx.x * 128;

    auto issue = [&](int it) {
        const int s = it % 3;
        const int k0 = it * 32;
        const uint32_t st = sb + s * STG_BYTES;
#pragma unroll
        for (int i = 0; i < 4; i++) {
            int c = tid + i * 256;           // 0..1023
            int row = c >> 2, seg = c & 3;
            uint32_t so = (uint32_t)((row * TLD + seg * 8) * 2);
            size_t g = (size_t)(m0 + row) * K + k0 + seg * 8;
            CP_ASYNC16(st + so, (const void*)(Ahi + g));
            CP_ASYNC16(st + SA_BYTES + so, (const void*)(Alo + g));
        }
#pragma unroll
        for (int i = 0; i < 2; i++) {
            int c = tid + i * 256;           // 0..511
            int row = c >> 2, seg = c & 3;
            uint32_t so = (uint32_t)((row * TLD + seg * 8) * 2);
            size_t g = (size_t)(n0 + row) * K + k0 + seg * 8;
            CP_ASYNC16(st + 2 * SA_BYTES + so, (const void*)(Bhi + g));
            CP_ASYNC16(st + 2 * SA_BYTES + SB_BYTES + so, (const void*)(Blo + g));
        }
        CP_COMMIT();
    };

    float acc[4][8][4];
#pragma unroll
    for (int mi = 0; mi < 4; mi++)
#pragma unroll
        for (int nj = 0; nj < 8; nj++)
#pragma unroll
            for (int r = 0; r < 4; r++) acc[mi][nj][r] = 0.f;

    const int nIter = K >> 5;
    issue(0);
    issue(1);

    for (int it = 0; it < nIter; ++it) {
        if (it + 1 < nIter) { CP_WAIT(1); } else { CP_WAIT(0); }
        __syncthreads();
        if (it + 2 < nIter) issue(it + 2);

        const uint32_t st = sb + (it % 3) * STG_BYTES;
        const uint32_t ah_b = st;
        const uint32_t al_b = st + SA_BYTES;
        const uint32_t bh_b = st + 2 * SA_BYTES;
        const uint32_t bl_b = bh_b + SB_BYTES;

#pragma unroll
        for (int ks = 0; ks < 2; ks++) {
            uint32_t ah[4][4], al[4][4];
            const int arow = wm * 64 + (lane & 15);
            const int acol = ks * 16 + (lane >> 4) * 8;
#pragma unroll
            for (int mi = 0; mi < 4; mi++) {
                uint32_t off = (uint32_t)(((arow + mi * 16) * TLD + acol) * 2);
                LDSM_X4(ah[mi][0], ah[mi][1], ah[mi][2], ah[mi][3], ah_b + off);
                LDSM_X4(al[mi][0], al[mi][1], al[mi][2], al[mi][3], al_b + off);
            }
            const int brow = wn * 64 + (lane & 7) + ((lane >> 4) << 3);
            const int bcol = ks * 16 + (((lane >> 3) & 1) << 3);
#pragma unroll
            for (int nt = 0; nt < 4; nt++) {
                uint32_t off = (uint32_t)(((brow + nt * 16) * TLD + bcol) * 2);
                uint32_t bh[4], bl[4];
                LDSM_X4(bh[0], bh[1], bh[2], bh[3], bh_b + off);
                LDSM_X4(bl[0], bl[1], bl[2], bl[3], bl_b + off);
#pragma unroll
                for (int mi = 0; mi < 4; mi++) {
                    MMA16816(acc[mi][2 * nt], ah[mi][0], ah[mi][1], ah[mi][2], ah[mi][3], bh[0], bh[1]);
                    MMA16816(acc[mi][2 * nt], ah[mi][0], ah[mi][1], ah[mi][2], ah[mi][3], bl[0], bl[1]);
                    MMA16816(acc[mi][2 * nt], al[mi][0], al[mi][1], al[mi][2], al[mi][3], bh[0], bh[1]);
                    MMA16816(acc[mi][2 * nt + 1], ah[mi][0], ah[mi][1], ah[mi][2], ah[mi][3], bh[2], bh[3]);
                    MMA16816(acc[mi][2 * nt + 1], ah[mi][0], ah[mi][1], ah[mi][2], ah[mi][3], bl[2], bl[3]);
                    MMA16816(acc[mi][2 * nt + 1], al[mi][0], al[mi][1], al[mi][2], al[mi][3], bh[2], bh[3]);
                }
            }
        }
    }

    // Epilogue
    const int er = lane >> 2, ec = (lane & 3) * 2;
#pragma unroll
    for (int mi = 0; mi < 4; mi++) {
        const int gr = m0 + wm * 64 + mi * 16 + er;
#pragma unroll
        for (int nj = 0; nj < 8; nj++) {
            const int gc = n0 + wn * 64 + nj * 8 + ec;
            if (Chi) {
#pragma unroll
                for (int half = 0; half < 2; half++) {
                    float f0 = acc[mi][nj][half * 2 + 0];
                    float f1 = acc[mi][nj][half * 2 + 1];
                    __nv_bfloat16 h0 = __float2bfloat16_rn(f0);
                    __nv_bfloat16 h1 = __float2bfloat16_rn(f1);
                    __nv_bfloat16 l0 = __float2bfloat16_rn(f0 - __bfloat162float(h0));
                    __nv_bfloat16 l1 = __float2bfloat16_rn(f1 - __bfloat162float(h1));
                    size_t o = (size_t)(gr + half * 8) * N + gc;
                    *(__nv_bfloat162*)(Chi + o) = __nv_bfloat162(h0, h1);
                    *(__nv_bfloat162*)(Clo + o) = __nv_bfloat162(l0, l1);
                }
            } else {
                *(float2*)(Cf + (size_t)gr * N + gc) =
                    make_float2(acc[mi][nj][0], acc[mi][nj][1]);
                *(float2*)(Cf + (size_t)(gr + 8) * N + gc) =
                    make_float2(acc[mi][nj][2], acc[mi][nj][3]);
            }
        }
    }
}

// ---------------------------------------------------------------------------
// Tensor-core flash attention on fused QKV buffer (stride QKVW).
// Writes bf16 hi/lo output directly (feeds O-projection GEMM).
// ---------------------------------------------------------------------------
#define LDQ 136
#define LDSF 76
#define LDP 72
#define AOFF_QH 0
#define AOFF_QL 17408
#define AKV_BASE 34816
#define AKV_STAGE 69632
#define AOFF_S  174080
#define AOFF_PH 193536
#define AOFF_PL 202752
#define AOFF_RM 211968
#define AOFF_RL 212224
#define AOFF_RC 212480
#define ATT_SMEM 212736

__global__ void __launch_bounds__(256, 1) attn_mma_kernel(
    const __nv_bfloat16* __restrict__ QKVh, const __nv_bfloat16* __restrict__ QKVl,
    __nv_bfloat16* __restrict__ Oh, __nv_bfloat16* __restrict__ Ol)
{
    extern __shared__ char sm[];
    const uint32_t sb = smem_u32(sm);
    float* rowM = (float*)(sm + AOFF_RM);
    float* rowL = (float*)(sm + AOFF_RL);
    float* rowC = (float*)(sm + AOFF_RC);

    const int tid = threadIdx.x;
    const int wid = tid >> 5, lane = tid & 31;
    const int wm = wid & 3;
    const int wn = wid >> 2;
    const int qt = 31 - (int)blockIdx.x;
    const int h = blockIdx.y;
    const int kvh = h >> 2;
    const int m0 = qt * 64;
    const float scale = 0.08838834764831845f;

    const int koff = HID_DIM + kvh * DH;        // K cols in fused buffer
    const int voff = HID_DIM + KVW + kvh * DH;  // V cols

    auto kv_issue = [&](int jt, int s) {
        const uint32_t st = sb + AKV_BASE + s * AKV_STAGE;
#pragma unroll
        for (int i = 0; i < 4; i++) {
            int idx = tid + i * 256;
            int row = idx >> 4, seg = idx & 15;
            uint32_t so = (uint32_t)((row * LDQ + seg * 8) * 2);
            size_t gK = (size_t)(jt * 64 + row) * QKVW + koff + seg * 8;
            size_t gV = (size_t)(jt * 64 + row) * QKVW + voff + seg * 8;
            CP_ASYNC16(st + 0 * 17408 + so, (const void*)(QKVh + gK));
            CP_ASYNC16(st + 1 * 17408 + so, (const void*)(QKVl + gK));
            CP_ASYNC16(st + 2 * 17408 + so, (const void*)(QKVh + gV));
            CP_ASYNC16(st + 3 * 17408 + so, (const void*)(QKVl + gV));
        }
        CP_COMMIT();
    };

    kv_issue(0, 0);

    {
        __nv_bfloat16* qh_s = (__nv_bfloat16*)(sm + AOFF_QH);
        __nv_bfloat16* ql_s = (__nv_bfloat16*)(sm + AOFF_QL);
#pragma unroll
        for (int i = 0; i < 4; i++) {
            int idx = tid + i * 256;
            int row = idx >> 4, seg = idx & 15;
            size_t g = (size_t)(m0 + row) * QKVW + h * DH + seg * 8;
            *(uint4*)(qh_s + row * LDQ + seg * 8) = *(const uint4*)(QKVh + g);
            *(uint4*)(ql_s + row * LDQ + seg * 8) = *(const uint4*)(QKVl + g);
        }
    }
    if (tid < 64) { rowM[tid] = -1e30f; rowL[tid] = 0.f; }

    float o[8][4];
#pragma unroll
    for (int j = 0; j < 8; j++)
#pragma unroll
        for (int r = 0; r < 4; r++) o[j][r] = 0.f;

    const int r0l = lane >> 2;
    const int c0l = (lane & 3) * 2;

    for (int jt = 0; jt <= qt; jt++) {
        const int s = jt & 1;
        CP_WAIT(0);
        __syncthreads();
        if (jt < qt) kv_issue(jt + 1, s ^ 1);

        const uint32_t kh_b = sb + AKV_BASE + s * AKV_STAGE;
        const uint32_t kl_b = kh_b + 17408;
        const uint32_t vh_b = kh_b + 2 * 17408;
        const uint32_t vl_b = kh_b + 3 * 17408;
        const uint32_t qh_b = sb + AOFF_QH, ql_b = sb + AOFF_QL;

        // S = Q K^T (bf16x3)
        {
            float sf[4][4];
#pragma unroll
            for (int j = 0; j < 4; j++)
#pragma unroll
                for (int r = 0; r < 4; r++) sf[j][r] = 0.f;

            const int ar = wm * 16 + (lane & 15);
#pragma unroll
            for (int k0 = 0; k0 < 128; k0 += 16) {
                const uint32_t aoff = (uint32_t)((ar * LDQ + k0 + (lane >> 4) * 8) * 2);
                uint32_t ah[4], al[4];
                LDSM_X4(ah[0], ah[1], ah[2], ah[3], qh_b + aoff);
                LDSM_X4(al[0], al[1], al[2], al[3], ql_b + aoff);
#pragma unroll
                for (int j = 0; j < 4; j++) {
                    const int bn = wn * 32 + j * 8 + (lane & 7);
                    const uint32_t boff =
                        (uint32_t)((bn * LDQ + k0 + ((lane & 8) ? 8 : 0)) * 2);
                    uint32_t bh[2], bl[2];
                    LDSM_X2(bh[0], bh[1], kh_b + boff);
                    LDSM_X2(bl[0], bl[1], kl_b + boff);
                    MMA16816(sf[j], ah[0], ah[1], ah[2], ah[3], bh[0], bh[1]);
                    MMA16816(sf[j], ah[0], ah[1], ah[2], ah[3], bl[0], bl[1]);
                    MMA16816(sf[j], al[0], al[1], al[2], al[3], bh[0], bh[1]);
                }
            }
            float* S_s = (float*)(sm + AOFF_S);
            const int sr0 = wm * 16 + r0l;
#pragma unroll
            for (int j = 0; j < 4; j++) {
                const int c = wn * 32 + j * 8 + c0l;
                S_s[sr0 * LDSF + c] = sf[j][0];
                S_s[sr0 * LDSF + c + 1] = sf[j][1];
                S_s[(sr0 + 8) * LDSF + c] = sf[j][2];
                S_s[(sr0 + 8) * LDSF + c + 1] = sf[j][3];
            }
        }
        __syncthreads();

        // online softmax, write P hi/lo
        {
            const int r = tid >> 2, sub = tid & 3;
            float* S_s = (float*)(sm + AOFF_S);
            __nv_bfloat16* ph_s = (__nv_bfloat16*)(sm + AOFF_PH);
            __nv_bfloat16* pl_s = (__nv_bfloat16*)(sm + AOFF_PL);
            const int gr = m0 + r, jn0 = jt * 64;
            float st[16];
            float mx = -1e30f;
#pragma unroll
            for (int c = 0; c < 16; c++) {
                int cc = sub * 16 + c;
                float v = S_s[r * LDSF + cc] * scale;
                if (jn0 + cc > gr) v = -1e30f;
                st[c] = v;
                mx = fmaxf(mx, v);
            }
            mx = fmaxf(mx, __shfl_xor_sync(0xFFFFFFFFu, mx, 1));
            mx = fmaxf(mx, __shfl_xor_sync(0xFFFFFFFFu, mx, 2));
            float mold = rowM[r];
            mx = fmaxf(mx, mold);
            float sum = 0.f;
#pragma unroll
            for (int c = 0; c < 16; c++) {
                float e = __expf(st[c] - mx);
                sum += e;
                __nv_bfloat16 hp = __float2bfloat16_rn(e);
                ph_s[r * LDP + sub * 16 + c] = hp;
                pl_s[r * LDP + sub * 16 + c] =
                    __float2bfloat16_rn(e - __bfloat162float(hp));
            }
            sum += __shfl_xor_sync(0xFFFFFFFFu, sum, 1);
            sum += __shfl_xor_sync(0xFFFFFFFFu, sum, 2);
            if (sub == 0) {
                float corr = __expf(mold - mx);
                rowC[r] = corr;
                rowL[r] = rowL[r] * corr + sum;
                rowM[r] = mx;
            }
        }
        __syncthreads();

        // O = O*corr + P V (bf16x3)
        {
            const float cr0 = rowC[wm * 16 + r0l];
            const float cr1 = rowC[wm * 16 + r0l + 8];
#pragma unroll
            for (int j = 0; j < 8; j++) {
                o[j][0] *= cr0; o[j][1] *= cr0;
                o[j][2] *= cr1; o[j][3] *= cr1;
            }
            const uint32_t ph_b = sb + AOFF_PH, pl_b = sb + AOFF_PL;
            const int ar = wm * 16 + (lane & 15);
#pragma unroll
            for (int k0 = 0; k0 < 64; k0 += 16) {
                const uint32_t aoff = (uint32_t)((ar * LDP + k0 + (lane >> 4) * 8) * 2);
                uint32_t ph[4], pl[4];
                LDSM_X4(ph[0], ph[1], ph[2], ph[3], ph_b + aoff);
                LDSM_X4(pl[0], pl[1], pl[2], pl[3], pl_b + aoff);
                const int vk = k0 + (lane & 15);
#pragma unroll
                for (int j = 0; j < 8; j++) {
                    const int d0 = wn * 64 + j * 8;
                    const uint32_t boff = (uint32_t)((vk * LDQ + d0) * 2);
                    uint32_t vh[2], vl[2];
                    LDSM_X2T(vh[0], vh[1], vh_b + boff);
                    LDSM_X2T(vl[0], vl[1], vl_b + boff);
                    MMA16816(o[j], ph[0], ph[1], ph[2], ph[3], vh[0], vh[1]);
                    MMA16816(o[j], pl[0], pl[1], pl[2], pl[3], vh[0], vh[1]);
                    MMA16816(o[j], ph[0], ph[1], ph[2], ph[3], vl[0], vl[1]);
                }
            }
        }
    }

    // normalize + store as bf16 hi/lo
    {
        const int gr0 = m0 + wm * 16 + r0l;
        const float il0 = 1.f / rowL[wm * 16 + r0l];
        const float il1 = 1.f / rowL[wm * 16 + r0l + 8];
#pragma unroll
        for (int j = 0; j < 8; j++) {
            const int d = h * DH + wn * 64 + j * 8 + c0l;
            float f0 = o[j][0] * il0, f1 = o[j][1] * il0;
            float f2 = o[j][2] * il1, f3 = o[j][3] * il1;
            __nv_bfloat16 h0 = __float2bfloat16_rn(f0);
            __nv_bfloat16 h1 = __float2bfloat16_rn(f1);
            __nv_bfloat16 h2 = __float2bfloat16_rn(f2);
            __nv_bfloat16 h3 = __float2bfloat16_rn(f3);
            size_t o0 = (size_t)gr0 * HID_DIM + d;
            size_t o1 = (size_t)(gr0 + 8) * HID_DIM + d;
            *(__nv_bfloat162*)(Oh + o0) = __nv_bfloat162(h0, h1);
            *(__nv_bfloat162*)(Oh + o1) = __nv_bfloat162(h2, h3);
            *(__nv_bfloat162*)(Ol + o0) = __nv_bfloat162(
                __float2bfloat16_rn(f0 - __bfloat162float(h0)),
                __float2bfloat16_rn(f1 - __bfloat162float(h1)));
            *(__nv_bfloat162*)(Ol + o1) = __nv_bfloat162(
                __float2bfloat16_rn(f2 - __bfloat162float(h2)),
                __float2bfloat16_rn(f3 - __bfloat162float(h3)));
        }
    }
}

// ---------------------------------------------------------------------------
// Orchestration
// ---------------------------------------------------------------------------
extern "C" void kernel_launch(void* const* d_in, const int* in_sizes, int n_in,
                              void* d_out, int out_size)
{
    const float* hidden = (const float*)d_in[0];
    const float* wq = (const float*)d_in[2];
    const float* wk = (const float*)d_in[3];
    const float* wv = (const float*)d_in[4];
    const float* wo = (const float*)d_in[5];
    float* out = (float*)d_out;

    __nv_bfloat16 *hh, *hl, *qkvh, *qkvl, *ath, *atl, *wqkvh, *wqkvl, *oth, *otl;
    cudaGetSymbolAddress((void**)&hh, g_hid_hi);    cudaGetSymbolAddress((void**)&hl, g_hid_lo);
    cudaGetSymbolAddress((void**)&qkvh, g_qkv_hi);  cudaGetSymbolAddress((void**)&qkvl, g_qkv_lo);
    cudaGetSymbolAddress((void**)&ath, g_at_hi);    cudaGetSymbolAddress((void**)&atl, g_at_lo);
    cudaGetSymbolAddress((void**)&wqkvh, g_wqkvT_hi); cudaGetSymbolAddress((void**)&wqkvl, g_wqkvT_lo);
    cudaGetSymbolAddress((void**)&oth, g_woT_hi);   cudaGetSymbolAddress((void**)&otl, g_woT_lo);

    cudaFuncSetAttribute(attn_mma_kernel, cudaFuncAttributeMaxDynamicSharedMemorySize, ATT_SMEM);
    cudaFuncSetAttribute(gemm_bf16x3_kernel, cudaFuncAttributeMaxDynamicSharedMemorySize, GEMM_SMEM);

    // hi/lo split of activations + transposed-split weights (Q,K,V fused)
    conv_hilo_kernel<<<(S_LEN * HID_DIM) / 1024, 256>>>(hidden, hh, hl, S_LEN * HID_DIM);
    dim3 tb(32, 8);
    conv_t_kernel<<<dim3(HID_DIM / 32, HID_DIM / 32), tb>>>(
        wq, wqkvh, wqkvl, HID_DIM, HID_DIM);
    conv_t_kernel<<<dim3(KVW / 32, HID_DIM / 32), tb>>>(
        wk, wqkvh + (size_t)HID_DIM * HID_DIM, wqkvl + (size_t)HID_DIM * HID_DIM,
        HID_DIM, KVW);
    conv_t_kernel<<<dim3(KVW / 32, HID_DIM / 32), tb>>>(
        wv, wqkvh + (size_t)(HID_DIM + KVW) * HID_DIM,
        wqkvl + (size_t)(HID_DIM + KVW) * HID_DIM, HID_DIM, KVW);
    conv_t_kernel<<<dim3(HID_DIM / 32, HID_DIM / 32), tb>>>(wo, oth, otl, HID_DIM, HID_DIM);

    // Fused QKV projection -> bf16 hi/lo epilogue
    gemm_bf16x3_kernel<<<dim3(QKVW / 128, S_LEN / 256), 256, GEMM_SMEM>>>(
        hh, hl, wqkvh, wqkvl, nullptr, qkvh, qkvl, S_LEN, QKVW, HID_DIM);

    // Attention (tensor cores) -> bf16 hi/lo output
    attn_mma_kernel<<<dim3(S_LEN / 64, NH), 256, ATT_SMEM>>>(qkvh, qkvl, ath, atl);

    // Output projection -> fp32 result
    gemm_bf16x3_kernel<<<dim3(HID_DIM / 128, S_LEN / 256), 256, GEMM_SMEM>>>(
        ath, atl, oth, otl, out, nullptr, nullptr, S_LEN, HID_DIM, HID_DIM);
}

// round 7
// speedup vs baseline: 6.2217x; 1.2717x over previous
#include <cuda_runtime.h>
#include <cuda_fp16.h>
#include <cstdint>
#include <math.h>

#define S_LEN 2048
#define HID_DIM 4096
#define NH 32
#define NKV 8
#define DH 128
#define KVW (NKV * DH)     // 1024
#define QKVW 6144          // fused Q(4096) + K(1024) + V(1024) width

// ---------------------------------------------------------------------------
// Scratch (device globals: allocation-free)
// ---------------------------------------------------------------------------
__device__ __half g_hid_hi[S_LEN * HID_DIM];
__device__ __half g_hid_lo[S_LEN * HID_DIM];
__device__ __half g_qkv_hi[S_LEN * QKVW];
__device__ __half g_qkv_lo[S_LEN * QKVW];
__device__ __half g_at_hi[S_LEN * HID_DIM];
__device__ __half g_at_lo[S_LEN * HID_DIM];
__device__ __half g_wqkvT[QKVW * HID_DIM];
__device__ __half g_woT[HID_DIM * HID_DIM];

// ---------------------------------------------------------------------------
// PTX helpers (baseline sm_80 PTX — safe on compute_103)
// ---------------------------------------------------------------------------
__device__ __forceinline__ uint32_t smem_u32(const void* p) {
    return (uint32_t)__cvta_generic_to_shared(p);
}
#define CP_ASYNC16(sa, gp) \
    asm volatile("cp.async.cg.shared.global [%0], [%1], 16;" :: "r"(sa), "l"(gp))
#define CP_COMMIT() asm volatile("cp.async.commit_group;" ::: "memory")
#define CP_WAIT(n)  asm volatile("cp.async.wait_group %0;" :: "n"(n) : "memory")

#define LDSM_X4(r0, r1, r2, r3, a) \
    asm volatile("ldmatrix.sync.aligned.m8n8.x4.shared.b16 {%0,%1,%2,%3},[%4];" \
        : "=r"(r0), "=r"(r1), "=r"(r2), "=r"(r3) : "r"(a))
#define LDSM_X2(r0, r1, a) \
    asm volatile("ldmatrix.sync.aligned.m8n8.x2.shared.b16 {%0,%1},[%2];" \
        : "=r"(r0), "=r"(r1) : "r"(a))
#define LDSM_X2T(r0, r1, a) \
    asm volatile("ldmatrix.sync.aligned.m8n8.x2.trans.shared.b16 {%0,%1},[%2];" \
        : "=r"(r0), "=r"(r1) : "r"(a))
#define MMA16816(d, a0, a1, a2, a3, b0, b1) \
    asm volatile("mma.sync.aligned.m16n8k16.row.col.f32.f16.f16.f32 " \
        "{%0,%1,%2,%3},{%4,%5,%6,%7},{%8,%9},{%0,%1,%2,%3};" \
        : "+f"((d)[0]), "+f"((d)[1]), "+f"((d)[2]), "+f"((d)[3]) \
        : "r"(a0), "r"(a1), "r"(a2), "r"(a3), "r"(b0), "r"(b1))

// ---------------------------------------------------------------------------
// Split fp32 -> (hi, lo) fp16, elementwise
// ---------------------------------------------------------------------------
__global__ void conv_hilo_kernel(const float* __restrict__ x,
                                 __half* __restrict__ hi,
                                 __half* __restrict__ lo, int n)
{
    int i = (blockIdx.x * blockDim.x + threadIdx.x) * 4;
    if (i >= n) return;
    float4 v = *(const float4*)(x + i);
    __half h0 = __float2half_rn(v.x);
    __half h1 = __float2half_rn(v.y);
    __half h2 = __float2half_rn(v.z);
    __half h3 = __float2half_rn(v.w);
    __half l0 = __float2half_rn(v.x - __half2float(h0));
    __half l1 = __float2half_rn(v.y - __half2float(h1));
    __half l2 = __float2half_rn(v.z - __half2float(h2));
    __half l3 = __float2half_rn(v.w - __half2float(h3));
    __half2* hp = (__half2*)(hi + i);
    __half2* lp = (__half2*)(lo + i);
    hp[0] = __half2(h0, h1); hp[1] = __half2(h2, h3);
    lp[0] = __half2(l0, l1); lp[1] = __half2(l2, l3);
}

// ---------------------------------------------------------------------------
// Transpose + round: B[K,N] fp32 -> T[N,K] fp16 (single precision weight)
// ---------------------------------------------------------------------------
__global__ void conv_t_kernel(const float* __restrict__ B,
                              __half* __restrict__ T, int K, int N)
{
    __shared__ float t[32][33];
    const int n0 = blockIdx.x * 32, k0 = blockIdx.y * 32;
    const int tx = threadIdx.x, ty = threadIdx.y;
#pragma unroll
    for (int i = 0; i < 32; i += 8)
        t[ty + i][tx] = B[(size_t)(k0 + ty + i) * N + n0 + tx];
    __syncthreads();
#pragma unroll
    for (int i = 0; i < 32; i += 8) {
        size_t o = (size_t)(n0 + ty + i) * K + k0 + tx;
        T[o] = __float2half_rn(t[tx][ty + i]);
    }
}

// ---------------------------------------------------------------------------
// fp16 split-A GEMM: C[M,N] = A[M,K] @ B[K,N], B given transposed [N,K] fp16.
// D = Ah*B + Al*B  (error = B's fp16 rounding, ~1e-4 rel).
// CTA tile 256x128, 8 warps (warp tile 64x64), k32 stages, 3-stage cp.async.
// ---------------------------------------------------------------------------
#define TLD 40
#define SA_BYTES (256 * TLD * 2)              // 20480
#define SB_BYTES (128 * TLD * 2)              // 10240
#define STG_BYTES (2 * SA_BYTES + SB_BYTES)   // 51200
#define GEMM_SMEM (3 * STG_BYTES)             // 153600

__global__ void __launch_bounds__(256, 1) gemm_fp16x2_kernel(
    const __half* __restrict__ Ahi, const __half* __restrict__ Alo,
    const __half* __restrict__ Bh,
    float* __restrict__ Cf,
    __half* __restrict__ Chi, __half* __restrict__ Clo,
    int M, int N, int K)
{
    extern __shared__ char smem[];
    const uint32_t sb = smem_u32(smem);
    const int tid = threadIdx.x;
    const int lane = tid & 31, wid = tid >> 5;
    const int wm = wid & 3, wn = wid >> 2;
    const int m0 = blockIdx.y * 256, n0 = blockIdx.x * 128;

    auto issue = [&](int it) {
        const int s = it % 3;
        const int k0 = it * 32;
        const uint32_t st = sb + s * STG_BYTES;
#pragma unroll
        for (int i = 0; i < 4; i++) {
            int c = tid + i * 256;           // 0..1023
            int row = c >> 2, seg = c & 3;
            uint32_t so = (uint32_t)((row * TLD + seg * 8) * 2);
            size_t g = (size_t)(m0 + row) * K + k0 + seg * 8;
            CP_ASYNC16(st + so, (const void*)(Ahi + g));
            CP_ASYNC16(st + SA_BYTES + so, (const void*)(Alo + g));
        }
#pragma unroll
        for (int i = 0; i < 2; i++) {
            int c = tid + i * 256;           // 0..511
            int row = c >> 2, seg = c & 3;
            uint32_t so = (uint32_t)((row * TLD + seg * 8) * 2);
            size_t g = (size_t)(n0 + row) * K + k0 + seg * 8;
            CP_ASYNC16(st + 2 * SA_BYTES + so, (const void*)(Bh + g));
        }
        CP_COMMIT();
    };

    float acc[4][8][4];
#pragma unroll
    for (int mi = 0; mi < 4; mi++)
#pragma unroll
        for (int nj = 0; nj < 8; nj++)
#pragma unroll
            for (int r = 0; r < 4; r++) acc[mi][nj][r] = 0.f;

    const int nIter = K >> 5;
    issue(0);
    issue(1);

    for (int it = 0; it < nIter; ++it) {
        if (it + 1 < nIter) { CP_WAIT(1); } else { CP_WAIT(0); }
        __syncthreads();
        if (it + 2 < nIter) issue(it + 2);

        const uint32_t st = sb + (it % 3) * STG_BYTES;
        const uint32_t ah_b = st;
        const uint32_t al_b = st + SA_BYTES;
        const uint32_t bh_b = st + 2 * SA_BYTES;

#pragma unroll
        for (int ks = 0; ks < 2; ks++) {
            uint32_t ah[4][4], al[4][4];
            const int arow = wm * 64 + (lane & 15);
            const int acol = ks * 16 + (lane >> 4) * 8;
#pragma unroll
            for (int mi = 0; mi < 4; mi++) {
                uint32_t off = (uint32_t)(((arow + mi * 16) * TLD + acol) * 2);
                LDSM_X4(ah[mi][0], ah[mi][1], ah[mi][2], ah[mi][3], ah_b + off);
                LDSM_X4(al[mi][0], al[mi][1], al[mi][2], al[mi][3], al_b + off);
            }
            const int brow = wn * 64 + (lane & 7) + ((lane >> 4) << 3);
            const int bcol = ks * 16 + (((lane >> 3) & 1) << 3);
#pragma unroll
            for (int nt = 0; nt < 4; nt++) {
                uint32_t off = (uint32_t)(((brow + nt * 16) * TLD + bcol) * 2);
                uint32_t bh[4];
                LDSM_X4(bh[0], bh[1], bh[2], bh[3], bh_b + off);
#pragma unroll
                for (int mi = 0; mi < 4; mi++) {
                    MMA16816(acc[mi][2 * nt], ah[mi][0], ah[mi][1], ah[mi][2], ah[mi][3], bh[0], bh[1]);
                    MMA16816(acc[mi][2 * nt], al[mi][0], al[mi][1], al[mi][2], al[mi][3], bh[0], bh[1]);
                    MMA16816(acc[mi][2 * nt + 1], ah[mi][0], ah[mi][1], ah[mi][2], ah[mi][3], bh[2], bh[3]);
                    MMA16816(acc[mi][2 * nt + 1], al[mi][0], al[mi][1], al[mi][2], al[mi][3], bh[2], bh[3]);
                }
            }
        }
    }

    // Epilogue
    const int er = lane >> 2, ec = (lane & 3) * 2;
#pragma unroll
    for (int mi = 0; mi < 4; mi++) {
        const int gr = m0 + wm * 64 + mi * 16 + er;
#pragma unroll
        for (int nj = 0; nj < 8; nj++) {
            const int gc = n0 + wn * 64 + nj * 8 + ec;
            if (Chi) {
#pragma unroll
                for (int half_ = 0; half_ < 2; half_++) {
                    float f0 = acc[mi][nj][half_ * 2 + 0];
                    float f1 = acc[mi][nj][half_ * 2 + 1];
                    __half h0 = __float2half_rn(f0);
                    __half h1 = __float2half_rn(f1);
                    __half l0 = __float2half_rn(f0 - __half2float(h0));
                    __half l1 = __float2half_rn(f1 - __half2float(h1));
                    size_t o = (size_t)(gr + half_ * 8) * N + gc;
                    *(__half2*)(Chi + o) = __half2(h0, h1);
                    *(__half2*)(Clo + o) = __half2(l0, l1);
                }
            } else {
                *(float2*)(Cf + (size_t)gr * N + gc) =
                    make_float2(acc[mi][nj][0], acc[mi][nj][1]);
                *(float2*)(Cf + (size_t)(gr + 8) * N + gc) =
                    make_float2(acc[mi][nj][2], acc[mi][nj][3]);
            }
        }
    }
}

// ---------------------------------------------------------------------------
// Tensor-core flash attention on fused QKV buffer (stride QKVW), fp16,
// 3-term compensation (hi/lo both sides). Writes fp16 hi/lo output.
// ---------------------------------------------------------------------------
#define LDQ 136
#define LDSF 76
#define LDP 72
#define AOFF_QH 0
#define AOFF_QL 17408
#define AKV_BASE 34816
#define AKV_STAGE 69632
#define AOFF_S  174080
#define AOFF_PH 193536
#define AOFF_PL 202752
#define AOFF_RM 211968
#define AOFF_RL 212224
#define AOFF_RC 212480
#define ATT_SMEM 212736

__global__ void __launch_bounds__(256, 1) attn_mma_kernel(
    const __half* __restrict__ QKVh, const __half* __restrict__ QKVl,
    __half* __restrict__ Oh, __half* __restrict__ Ol)
{
    extern __shared__ char sm[];
    const uint32_t sb = smem_u32(sm);
    float* rowM = (float*)(sm + AOFF_RM);
    float* rowL = (float*)(sm + AOFF_RL);
    float* rowC = (float*)(sm + AOFF_RC);

    const int tid = threadIdx.x;
    const int wid = tid >> 5, lane = tid & 31;
    const int wm = wid & 3;
    const int wn = wid >> 2;
    const int qt = 31 - (int)blockIdx.x;
    const int h = blockIdx.y;
    const int kvh = h >> 2;
    const int m0 = qt * 64;
    const float scale = 0.08838834764831845f;

    const int koff = HID_DIM + kvh * DH;
    const int voff = HID_DIM + KVW + kvh * DH;

    auto kv_issue = [&](int jt, int s) {
        const uint32_t st = sb + AKV_BASE + s * AKV_STAGE;
#pragma unroll
        for (int i = 0; i < 4; i++) {
            int idx = tid + i * 256;
            int row = idx >> 4, seg = idx & 15;
            uint32_t so = (uint32_t)((row * LDQ + seg * 8) * 2);
            size_t gK = (size_t)(jt * 64 + row) * QKVW + koff + seg * 8;
            size_t gV = (size_t)(jt * 64 + row) * QKVW + voff + seg * 8;
            CP_ASYNC16(st + 0 * 17408 + so, (const void*)(QKVh + gK));
            CP_ASYNC16(st + 1 * 17408 + so, (const void*)(QKVl + gK));
            CP_ASYNC16(st + 2 * 17408 + so, (const void*)(QKVh + gV));
            CP_ASYNC16(st + 3 * 17408 + so, (const void*)(QKVl + gV));
        }
        CP_COMMIT();
    };

    kv_issue(0, 0);

    {
        __half* qh_s = (__half*)(sm + AOFF_QH);
        __half* ql_s = (__half*)(sm + AOFF_QL);
#pragma unroll
        for (int i = 0; i < 4; i++) {
            int idx = tid + i * 256;
            int row = idx >> 4, seg = idx & 15;
            size_t g = (size_t)(m0 + row) * QKVW + h * DH + seg * 8;
            *(uint4*)(qh_s + row * LDQ + seg * 8) = *(const uint4*)(QKVh + g);
            *(uint4*)(ql_s + row * LDQ + seg * 8) = *(const uint4*)(QKVl + g);
        }
    }
    if (tid < 64) { rowM[tid] = -1e30f; rowL[tid] = 0.f; }

    float o[8][4];
#pragma unroll
    for (int j = 0; j < 8; j++)
#pragma unroll
        for (int r = 0; r < 4; r++) o[j][r] = 0.f;

    const int r0l = lane >> 2;
    const int c0l = (lane & 3) * 2;

    for (int jt = 0; jt <= qt; jt++) {
        const int s = jt & 1;
        CP_WAIT(0);
        __syncthreads();
        if (jt < qt) kv_issue(jt + 1, s ^ 1);

        const uint32_t kh_b = sb + AKV_BASE + s * AKV_STAGE;
        const uint32_t kl_b = kh_b + 17408;
        const uint32_t vh_b = kh_b + 2 * 17408;
        const uint32_t vl_b = kh_b + 3 * 17408;
        const uint32_t qh_b = sb + AOFF_QH, ql_b = sb + AOFF_QL;

        // S = Q K^T (3-term fp16)
        {
            float sf[4][4];
#pragma unroll
            for (int j = 0; j < 4; j++)
#pragma unroll
                for (int r = 0; r < 4; r++) sf[j][r] = 0.f;

            const int ar = wm * 16 + (lane & 15);
#pragma unroll
            for (int k0 = 0; k0 < 128; k0 += 16) {
                const uint32_t aoff = (uint32_t)((ar * LDQ + k0 + (lane >> 4) * 8) * 2);
                uint32_t ah[4], al[4];
                LDSM_X4(ah[0], ah[1], ah[2], ah[3], qh_b + aoff);
                LDSM_X4(al[0], al[1], al[2], al[3], ql_b + aoff);
#pragma unroll
                for (int j = 0; j < 4; j++) {
                    const int bn = wn * 32 + j * 8 + (lane & 7);
                    const uint32_t boff =
                        (uint32_t)((bn * LDQ + k0 + ((lane & 8) ? 8 : 0)) * 2);
                    uint32_t bh[2], bl[2];
                    LDSM_X2(bh[0], bh[1], kh_b + boff);
                    LDSM_X2(bl[0], bl[1], kl_b + boff);
                    MMA16816(sf[j], ah[0], ah[1], ah[2], ah[3], bh[0], bh[1]);
                    MMA16816(sf[j], ah[0], ah[1], ah[2], ah[3], bl[0], bl[1]);
                    MMA16816(sf[j], al[0], al[1], al[2], al[3], bh[0], bh[1]);
                }
            }
            float* S_s = (float*)(sm + AOFF_S);
            const int sr0 = wm * 16 + r0l;
#pragma unroll
            for (int j = 0; j < 4; j++) {
                const int c = wn * 32 + j * 8 + c0l;
                S_s[sr0 * LDSF + c] = sf[j][0];
                S_s[sr0 * LDSF + c + 1] = sf[j][1];
                S_s[(sr0 + 8) * LDSF + c] = sf[j][2];
                S_s[(sr0 + 8) * LDSF + c + 1] = sf[j][3];
            }
        }
        __syncthreads();

        // online softmax, write P hi/lo
        {
            const int r = tid >> 2, sub = tid & 3;
            float* S_s = (float*)(sm + AOFF_S);
            __half* ph_s = (__half*)(sm + AOFF_PH);
            __half* pl_s = (__half*)(sm + AOFF_PL);
            const int gr = m0 + r, jn0 = jt * 64;
            float st[16];
            float mx = -1e30f;
#pragma unroll
            for (int c = 0; c < 16; c++) {
                int cc = sub * 16 + c;
                float v = S_s[r * LDSF + cc] * scale;
                if (jn0 + cc > gr) v = -1e30f;
                st[c] = v;
                mx = fmaxf(mx, v);
            }
            mx = fmaxf(mx, __shfl_xor_sync(0xFFFFFFFFu, mx, 1));
            mx = fmaxf(mx, __shfl_xor_sync(0xFFFFFFFFu, mx, 2));
            float mold = rowM[r];
            mx = fmaxf(mx, mold);
            float sum = 0.f;
#pragma unroll
            for (int c = 0; c < 16; c++) {
                float e = __expf(st[c] - mx);
                sum += e;
                __half hp = __float2half_rn(e);
                ph_s[r * LDP + sub * 16 + c] = hp;
                pl_s[r * LDP + sub * 16 + c] =
                    __float2half_rn(e - __half2float(hp));
            }
            sum += __shfl_xor_sync(0xFFFFFFFFu, sum, 1);
            sum += __shfl_xor_sync(0xFFFFFFFFu, sum, 2);
            if (sub == 0) {
                float corr = __expf(mold - mx);
                rowC[r] = corr;
                rowL[r] = rowL[r] * corr + sum;
                rowM[r] = mx;
            }
        }
        __syncthreads();

        // O = O*corr + P V (3-term fp16)
        {
            const float cr0 = rowC[wm * 16 + r0l];
            const float cr1 = rowC[wm * 16 + r0l + 8];
#pragma unroll
            for (int j = 0; j < 8; j++) {
                o[j][0] *= cr0; o[j][1] *= cr0;
                o[j][2] *= cr1; o[j][3] *= cr1;
            }
            const uint32_t ph_b = sb + AOFF_PH, pl_b = sb + AOFF_PL;
            const int ar = wm * 16 + (lane & 15);
#pragma unroll
            for (int k0 = 0; k0 < 64; k0 += 16) {
                const uint32_t aoff = (uint32_t)((ar * LDP + k0 + (lane >> 4) * 8) * 2);
                uint32_t ph[4], pl[4];
                LDSM_X4(ph[0], ph[1], ph[2], ph[3], ph_b + aoff);
                LDSM_X4(pl[0], pl[1], pl[2], pl[3], pl_b + aoff);
                const int vk = k0 + (lane & 15);
#pragma unroll
                for (int j = 0; j < 8; j++) {
                    const int d0 = wn * 64 + j * 8;
                    const uint32_t boff = (uint32_t)((vk * LDQ + d0) * 2);
                    uint32_t vh[2], vl[2];
                    LDSM_X2T(vh[0], vh[1], vh_b + boff);
                    LDSM_X2T(vl[0], vl[1], vl_b + boff);
                    MMA16816(o[j], ph[0], ph[1], ph[2], ph[3], vh[0], vh[1]);
                    MMA16816(o[j], pl[0], pl[1], pl[2], pl[3], vh[0], vh[1]);
                    MMA16816(o[j], ph[0], ph[1], ph[2], ph[3], vl[0], vl[1]);
                }
            }
        }
    }

    // normalize + store as fp16 hi/lo
    {
        const int gr0 = m0 + wm * 16 + r0l;
        const float il0 = 1.f / rowL[wm * 16 + r0l];
        const float il1 = 1.f / rowL[wm * 16 + r0l + 8];
#pragma unroll
        for (int j = 0; j < 8; j++) {
            const int d = h * DH + wn * 64 + j * 8 + c0l;
            float f0 = o[j][0] * il0, f1 = o[j][1] * il0;
            float f2 = o[j][2] * il1, f3 = o[j][3] * il1;
            __half h0 = __float2half_rn(f0);
            __half h1 = __float2half_rn(f1);
            __half h2 = __float2half_rn(f2);
            __half h3 = __float2half_rn(f3);
            size_t o0 = (size_t)gr0 * HID_DIM + d;
            size_t o1 = (size_t)(gr0 + 8) * HID_DIM + d;
            *(__half2*)(Oh + o0) = __half2(h0, h1);
            *(__half2*)(Oh + o1) = __half2(h2, h3);
            *(__half2*)(Ol + o0) = __half2(
                __float2half_rn(f0 - __half2float(h0)),
                __float2half_rn(f1 - __half2float(h1)));
            *(__half2*)(Ol + o1) = __half2(
                __float2half_rn(f2 - __half2float(h2)),
                __float2half_rn(f3 - __half2float(h3)));
        }
    }
}

// ---------------------------------------------------------------------------
// Orchestration
// ---------------------------------------------------------------------------
extern "C" void kernel_launch(void* const* d_in, const int* in_sizes, int n_in,
                              void* d_out, int out_size)
{
    const float* hidden = (const float*)d_in[0];
    const float* wq = (const float*)d_in[2];
    const float* wk = (const float*)d_in[3];
    const float* wv = (const float*)d_in[4];
    const float* wo = (const float*)d_in[5];
    float* out = (float*)d_out;

    __half *hh, *hl, *qkvh, *qkvl, *ath, *atl, *wqkv, *wot;
    cudaGetSymbolAddress((void**)&hh, g_hid_hi);    cudaGetSymbolAddress((void**)&hl, g_hid_lo);
    cudaGetSymbolAddress((void**)&qkvh, g_qkv_hi);  cudaGetSymbolAddress((void**)&qkvl, g_qkv_lo);
    cudaGetSymbolAddress((void**)&ath, g_at_hi);    cudaGetSymbolAddress((void**)&atl, g_at_lo);
    cudaGetSymbolAddress((void**)&wqkv, g_wqkvT);   cudaGetSymbolAddress((void**)&wot, g_woT);

    cudaFuncSetAttribute(attn_mma_kernel, cudaFuncAttributeMaxDynamicSharedMemorySize, ATT_SMEM);
    cudaFuncSetAttribute(gemm_fp16x2_kernel, cudaFuncAttributeMaxDynamicSharedMemorySize, GEMM_SMEM);

    // hi/lo split of activations + transposed fp16 weights (Q,K,V fused)
    conv_hilo_kernel<<<(S_LEN * HID_DIM) / 1024, 256>>>(hidden, hh, hl, S_LEN * HID_DIM);
    dim3 tb(32, 8);
    conv_t_kernel<<<dim3(HID_DIM / 32, HID_DIM / 32), tb>>>(wq, wqkv, HID_DIM, HID_DIM);
    conv_t_kernel<<<dim3(KVW / 32, HID_DIM / 32), tb>>>(
        wk, wqkv + (size_t)HID_DIM * HID_DIM, HID_DIM, KVW);
    conv_t_kernel<<<dim3(KVW / 32, HID_DIM / 32), tb>>>(
        wv, wqkv + (size_t)(HID_DIM + KVW) * HID_DIM, HID_DIM, KVW);
    conv_t_kernel<<<dim3(HID_DIM / 32, HID_DIM / 32), tb>>>(wo, wot, HID_DIM, HID_DIM);

    // Fused QKV projection -> fp16 hi/lo epilogue
    gemm_fp16x2_kernel<<<dim3(QKVW / 128, S_LEN / 256), 256, GEMM_SMEM>>>(
        hh, hl, wqkv, nullptr, qkvh, qkvl, S_LEN, QKVW, HID_DIM);

    // Attention (tensor cores) -> fp16 hi/lo output
    attn_mma_kernel<<<dim3(S_LEN / 64, NH), 256, ATT_SMEM>>>(qkvh, qkvl, ath, atl);

    // Output projection -> fp32 result
    gemm_fp16x2_kernel<<<dim3(HID_DIM / 128, S_LEN / 256), 256, GEMM_SMEM>>>(
        ath, atl, wot, out, nullptr, nullptr, S_LEN, HID_DIM, HID_DIM);
}

// round 8
// speedup vs baseline: 6.3497x; 1.0206x over previous
#include <cuda_runtime.h>
#include <cuda_fp16.h>
#include <cstdint>
#include <math.h>

#define S_LEN 2048
#define HID_DIM 4096
#define NH 32
#define NKV 8
#define DH 128
#define KVW (NKV * DH)     // 1024
#define QKVW 6144          // fused Q(4096) + K(1024) + V(1024) width

// ---------------------------------------------------------------------------
// Scratch (device globals: allocation-free)
// ---------------------------------------------------------------------------
__device__ __half g_hid_hi[S_LEN * HID_DIM];
__device__ __half g_hid_lo[S_LEN * HID_DIM];
__device__ __half g_qkv_hi[S_LEN * QKVW];
__device__ __half g_qkv_lo[S_LEN * QKVW];
__device__ __half g_at_hi[S_LEN * HID_DIM];
__device__ __half g_at_lo[S_LEN * HID_DIM];
__device__ __half g_wqkvT[QKVW * HID_DIM];
__device__ __half g_woT[HID_DIM * HID_DIM];

// ---------------------------------------------------------------------------
// PTX helpers (baseline sm_80 PTX — safe on compute_103)
// ---------------------------------------------------------------------------
__device__ __forceinline__ uint32_t smem_u32(const void* p) {
    return (uint32_t)__cvta_generic_to_shared(p);
}
#define CP_ASYNC16(sa, gp) \
    asm volatile("cp.async.cg.shared.global [%0], [%1], 16;" :: "r"(sa), "l"(gp))
#define CP_COMMIT() asm volatile("cp.async.commit_group;" ::: "memory")
#define CP_WAIT(n)  asm volatile("cp.async.wait_group %0;" :: "n"(n) : "memory")

#define LDSM_X4(r0, r1, r2, r3, a) \
    asm volatile("ldmatrix.sync.aligned.m8n8.x4.shared.b16 {%0,%1,%2,%3},[%4];" \
        : "=r"(r0), "=r"(r1), "=r"(r2), "=r"(r3) : "r"(a))
#define LDSM_X4T(r0, r1, r2, r3, a) \
    asm volatile("ldmatrix.sync.aligned.m8n8.x4.trans.shared.b16 {%0,%1,%2,%3},[%4];" \
        : "=r"(r0), "=r"(r1), "=r"(r2), "=r"(r3) : "r"(a))
#define MMA16816(d, a0, a1, a2, a3, b0, b1) \
    asm volatile("mma.sync.aligned.m16n8k16.row.col.f32.f16.f16.f32 " \
        "{%0,%1,%2,%3},{%4,%5,%6,%7},{%8,%9},{%0,%1,%2,%3};" \
        : "+f"((d)[0]), "+f"((d)[1]), "+f"((d)[2]), "+f"((d)[3]) \
        : "r"(a0), "r"(a1), "r"(a2), "r"(a3), "r"(b0), "r"(b1))

__device__ __forceinline__ uint32_t pack_h2(__half a, __half b) {
    __half2 h = __halves2half2(a, b);
    return *(uint32_t*)&h;
}

// ---------------------------------------------------------------------------
// Split fp32 -> (hi, lo) fp16, elementwise
// ---------------------------------------------------------------------------
__global__ void conv_hilo_kernel(const float* __restrict__ x,
                                 __half* __restrict__ hi,
                                 __half* __restrict__ lo, int n)
{
    int i = (blockIdx.x * blockDim.x + threadIdx.x) * 4;
    if (i >= n) return;
    float4 v = *(const float4*)(x + i);
    __half h0 = __float2half_rn(v.x);
    __half h1 = __float2half_rn(v.y);
    __half h2 = __float2half_rn(v.z);
    __half h3 = __float2half_rn(v.w);
    __half l0 = __float2half_rn(v.x - __half2float(h0));
    __half l1 = __float2half_rn(v.y - __half2float(h1));
    __half l2 = __float2half_rn(v.z - __half2float(h2));
    __half l3 = __float2half_rn(v.w - __half2float(h3));
    __half2* hp = (__half2*)(hi + i);
    __half2* lp = (__half2*)(lo + i);
    hp[0] = __half2(h0, h1); hp[1] = __half2(h2, h3);
    lp[0] = __half2(l0, l1); lp[1] = __half2(l2, l3);
}

// ---------------------------------------------------------------------------
// Transpose + round: B[K,N] fp32 -> T[N,K] fp16
// ---------------------------------------------------------------------------
__global__ void conv_t_kernel(const float* __restrict__ B,
                              __half* __restrict__ T, int K, int N)
{
    __shared__ float t[32][33];
    const int n0 = blockIdx.x * 32, k0 = blockIdx.y * 32;
    const int tx = threadIdx.x, ty = threadIdx.y;
#pragma unroll
    for (int i = 0; i < 32; i += 8)
        t[ty + i][tx] = B[(size_t)(k0 + ty + i) * N + n0 + tx];
    __syncthreads();
#pragma unroll
    for (int i = 0; i < 32; i += 8) {
        size_t o = (size_t)(n0 + ty + i) * K + k0 + tx;
        T[o] = __float2half_rn(t[tx][ty + i]);
    }
}

// ---------------------------------------------------------------------------
// fp16 split-A GEMM (unchanged from R7): D = Ah*B + Al*B
// CTA tile 256x128, warp tile 64x64, 3-stage cp.async.
// ---------------------------------------------------------------------------
#define TLD 40
#define SA_BYTES (256 * TLD * 2)
#define SB_BYTES (128 * TLD * 2)
#define STG_BYTES (2 * SA_BYTES + SB_BYTES)
#define GEMM_SMEM (3 * STG_BYTES)

__global__ void __launch_bounds__(256, 1) gemm_fp16x2_kernel(
    const __half* __restrict__ Ahi, const __half* __restrict__ Alo,
    const __half* __restrict__ Bh,
    float* __restrict__ Cf,
    __half* __restrict__ Chi, __half* __restrict__ Clo,
    int M, int N, int K)
{
    extern __shared__ char smem[];
    const uint32_t sb = smem_u32(smem);
    const int tid = threadIdx.x;
    const int lane = tid & 31, wid = tid >> 5;
    const int wm = wid & 3, wn = wid >> 2;
    const int m0 = blockIdx.y * 256, n0 = blockIdx.x * 128;

    auto issue = [&](int it) {
        const int s = it % 3;
        const int k0 = it * 32;
        const uint32_t st = sb + s * STG_BYTES;
#pragma unroll
        for (int i = 0; i < 4; i++) {
            int c = tid + i * 256;
            int row = c >> 2, seg = c & 3;
            uint32_t so = (uint32_t)((row * TLD + seg * 8) * 2);
            size_t g = (size_t)(m0 + row) * K + k0 + seg * 8;
            CP_ASYNC16(st + so, (const void*)(Ahi + g));
            CP_ASYNC16(st + SA_BYTES + so, (const void*)(Alo + g));
        }
#pragma unroll
        for (int i = 0; i < 2; i++) {
            int c = tid + i * 256;
            int row = c >> 2, seg = c & 3;
            uint32_t so = (uint32_t)((row * TLD + seg * 8) * 2);
            size_t g = (size_t)(n0 + row) * K + k0 + seg * 8;
            CP_ASYNC16(st + 2 * SA_BYTES + so, (const void*)(Bh + g));
        }
        CP_COMMIT();
    };

    float acc[4][8][4];
#pragma unroll
    for (int mi = 0; mi < 4; mi++)
#pragma unroll
        for (int nj = 0; nj < 8; nj++)
#pragma unroll
            for (int r = 0; r < 4; r++) acc[mi][nj][r] = 0.f;

    const int nIter = K >> 5;
    issue(0);
    issue(1);

    for (int it = 0; it < nIter; ++it) {
        if (it + 1 < nIter) { CP_WAIT(1); } else { CP_WAIT(0); }
        __syncthreads();
        if (it + 2 < nIter) issue(it + 2);

        const uint32_t st = sb + (it % 3) * STG_BYTES;
        const uint32_t ah_b = st;
        const uint32_t al_b = st + SA_BYTES;
        const uint32_t bh_b = st + 2 * SA_BYTES;

#pragma unroll
        for (int ks = 0; ks < 2; ks++) {
            uint32_t ah[4][4], al[4][4];
            const int arow = wm * 64 + (lane & 15);
            const int acol = ks * 16 + (lane >> 4) * 8;
#pragma unroll
            for (int mi = 0; mi < 4; mi++) {
                uint32_t off = (uint32_t)(((arow + mi * 16) * TLD + acol) * 2);
                LDSM_X4(ah[mi][0], ah[mi][1], ah[mi][2], ah[mi][3], ah_b + off);
                LDSM_X4(al[mi][0], al[mi][1], al[mi][2], al[mi][3], al_b + off);
            }
            const int brow = wn * 64 + (lane & 7) + ((lane >> 4) << 3);
            const int bcol = ks * 16 + (((lane >> 3) & 1) << 3);
#pragma unroll
            for (int nt = 0; nt < 4; nt++) {
                uint32_t off = (uint32_t)(((brow + nt * 16) * TLD + bcol) * 2);
                uint32_t bh[4];
                LDSM_X4(bh[0], bh[1], bh[2], bh[3], bh_b + off);
#pragma unroll
                for (int mi = 0; mi < 4; mi++) {
                    MMA16816(acc[mi][2 * nt], ah[mi][0], ah[mi][1], ah[mi][2], ah[mi][3], bh[0], bh[1]);
                    MMA16816(acc[mi][2 * nt], al[mi][0], al[mi][1], al[mi][2], al[mi][3], bh[0], bh[1]);
                    MMA16816(acc[mi][2 * nt + 1], ah[mi][0], ah[mi][1], ah[mi][2], ah[mi][3], bh[2], bh[3]);
                    MMA16816(acc[mi][2 * nt + 1], al[mi][0], al[mi][1], al[mi][2], al[mi][3], bh[2], bh[3]);
                }
            }
        }
    }

    const int er = lane >> 2, ec = (lane & 3) * 2;
#pragma unroll
    for (int mi = 0; mi < 4; mi++) {
        const int gr = m0 + wm * 64 + mi * 16 + er;
#pragma unroll
        for (int nj = 0; nj < 8; nj++) {
            const int gc = n0 + wn * 64 + nj * 8 + ec;
            if (Chi) {
#pragma unroll
                for (int half_ = 0; half_ < 2; half_++) {
                    float f0 = acc[mi][nj][half_ * 2 + 0];
                    float f1 = acc[mi][nj][half_ * 2 + 1];
                    __half h0 = __float2half_rn(f0);
                    __half h1 = __float2half_rn(f1);
                    __half l0 = __float2half_rn(f0 - __half2float(h0));
                    __half l1 = __float2half_rn(f1 - __half2float(h1));
                    size_t o = (size_t)(gr + half_ * 8) * N + gc;
                    *(__half2*)(Chi + o) = __half2(h0, h1);
                    *(__half2*)(Clo + o) = __half2(l0, l1);
                }
            } else {
                *(float2*)(Cf + (size_t)gr * N + gc) =
                    make_float2(acc[mi][nj][0], acc[mi][nj][1]);
                *(float2*)(Cf + (size_t)(gr + 8) * N + gc) =
                    make_float2(acc[mi][nj][2], acc[mi][nj][3]);
            }
        }
    }
}

// ---------------------------------------------------------------------------
// Register-resident FA2 attention: 128-query tile/CTA, warp owns 16 rows x
// full 64-key width. S frags in regs, warp-local softmax (shfl), P->A frag
// reuse, 3-term fp16 compensation. 1 sync per KV iteration.
// ---------------------------------------------------------------------------
#define LDQ 136
#define AQH 0
#define AQL 34816
#define AKV 69632
#define AMAT 17408
#define AKV_STG (4 * AMAT)           // 69632
#define ATT_SMEM (AKV + 2 * AKV_STG) // 208896

__global__ void __launch_bounds__(256, 1) attn_mma_kernel(
    const __half* __restrict__ QKVh, const __half* __restrict__ QKVl,
    __half* __restrict__ Oh, __half* __restrict__ Ol)
{
    extern __shared__ char sm[];
    const uint32_t sb = smem_u32(sm);
    const int tid = threadIdx.x;
    const int wid = tid >> 5, lane = tid & 31;
    const int qt = 15 - (int)blockIdx.x;     // heavy tiles first
    const int h = blockIdx.y;
    const int kvh = h >> 2;
    const int m0 = qt * 128;
    const int wrow = wid * 16;
    const float scale = 0.08838834764831845f;

    const int koff = HID_DIM + kvh * DH;
    const int voff = HID_DIM + KVW + kvh * DH;

    auto kv_issue = [&](int jt, int s) {
        const uint32_t st = sb + AKV + s * AKV_STG;
#pragma unroll
        for (int i = 0; i < 4; i++) {
            int idx = tid + i * 256;
            int row = idx >> 4, seg = idx & 15;
            uint32_t so = (uint32_t)((row * LDQ + seg * 8) * 2);
            size_t gK = (size_t)(jt * 64 + row) * QKVW + koff + seg * 8;
            size_t gV = (size_t)(jt * 64 + row) * QKVW + voff + seg * 8;
            CP_ASYNC16(st + 0 * AMAT + so, (const void*)(QKVh + gK));
            CP_ASYNC16(st + 1 * AMAT + so, (const void*)(QKVl + gK));
            CP_ASYNC16(st + 2 * AMAT + so, (const void*)(QKVh + gV));
            CP_ASYNC16(st + 3 * AMAT + so, (const void*)(QKVl + gV));
        }
        CP_COMMIT();
    };

    kv_issue(0, 0);

    // Q tile (128 rows) hi/lo -> smem
    {
        __half* qh_s = (__half*)(sm + AQH);
        __half* ql_s = (__half*)(sm + AQL);
#pragma unroll
        for (int i = 0; i < 8; i++) {
            int idx = tid + i * 256;
            int row = idx >> 4, seg = idx & 15;
            size_t g = (size_t)(m0 + row) * QKVW + h * DH + seg * 8;
            *(uint4*)(qh_s + row * LDQ + seg * 8) = *(const uint4*)(QKVh + g);
            *(uint4*)(ql_s + row * LDQ + seg * 8) = *(const uint4*)(QKVl + g);
        }
    }

    float o[16][4];
#pragma unroll
    for (int nf = 0; nf < 16; nf++)
#pragma unroll
        for (int r = 0; r < 4; r++) o[nf][r] = 0.f;
    float rM0 = -1e30f, rM1 = -1e30f, rL0 = 0.f, rL1 = 0.f;

    const int r0l = lane >> 2, c0l = (lane & 3) * 2;
    const int lrow = lane & 15, lcolh = (lane >> 4) * 8;
    const int gq0 = m0 + wrow + r0l, gq1 = gq0 + 8;
    const int nIter = 2 * qt + 2;

    for (int jt = 0; jt < nIter; jt++) {
        const int s = jt & 1;
        CP_WAIT(0);
        __syncthreads();
        if (jt + 1 < nIter) kv_issue(jt + 1, s ^ 1);

        const uint32_t kh_b = sb + AKV + s * AKV_STG;
        const uint32_t kl_b = kh_b + AMAT;
        const uint32_t vh_b = kh_b + 2 * AMAT;
        const uint32_t vl_b = kh_b + 3 * AMAT;

        // ---- S = Q K^T (3-term), S frags stay in registers ----
        float sf[8][4];
#pragma unroll
        for (int jj = 0; jj < 8; jj++)
#pragma unroll
            for (int r = 0; r < 4; r++) sf[jj][r] = 0.f;

#pragma unroll
        for (int ks = 0; ks < 8; ks++) {
            const int k0 = ks * 16;
            uint32_t aoff = (uint32_t)(((wrow + lrow) * LDQ + k0 + lcolh) * 2);
            uint32_t qh[4], ql[4];
            LDSM_X4(qh[0], qh[1], qh[2], qh[3], sb + AQH + aoff);
            LDSM_X4(ql[0], ql[1], ql[2], ql[3], sb + AQL + aoff);
#pragma unroll
            for (int jb = 0; jb < 4; jb++) {
                uint32_t boff = (uint32_t)(((jb * 16 + lrow) * LDQ + k0 + lcolh) * 2);
                uint32_t bh[4], bl[4];
                LDSM_X4(bh[0], bh[1], bh[2], bh[3], kh_b + boff);
                LDSM_X4(bl[0], bl[1], bl[2], bl[3], kl_b + boff);
                MMA16816(sf[2 * jb], qh[0], qh[1], qh[2], qh[3], bh[0], bh[2]);
                MMA16816(sf[2 * jb], qh[0], qh[1], qh[2], qh[3], bl[0], bl[2]);
                MMA16816(sf[2 * jb], ql[0], ql[1], ql[2], ql[3], bh[0], bh[2]);
                MMA16816(sf[2 * jb + 1], qh[0], qh[1], qh[2], qh[3], bh[1], bh[3]);
                MMA16816(sf[2 * jb + 1], qh[0], qh[1], qh[2], qh[3], bl[1], bl[3]);
                MMA16816(sf[2 * jb + 1], ql[0], ql[1], ql[2], ql[3], bh[1], bh[3]);
            }
        }

        // ---- mask + scale + warp-local online softmax ----
        const int jn0 = jt * 64;
        float mx0 = -1e30f, mx1 = -1e30f;
#pragma unroll
        for (int jj = 0; jj < 8; jj++) {
            int cb = jn0 + jj * 8 + c0l;
            sf[jj][0] = (cb > gq0) ? -1e30f : sf[jj][0] * scale;
            sf[jj][1] = (cb + 1 > gq0) ? -1e30f : sf[jj][1] * scale;
            sf[jj][2] = (cb > gq1) ? -1e30f : sf[jj][2] * scale;
            sf[jj][3] = (cb + 1 > gq1) ? -1e30f : sf[jj][3] * scale;
            mx0 = fmaxf(mx0, fmaxf(sf[jj][0], sf[jj][1]));
            mx1 = fmaxf(mx1, fmaxf(sf[jj][2], sf[jj][3]));
        }
        mx0 = fmaxf(mx0, __shfl_xor_sync(0xFFFFFFFFu, mx0, 1));
        mx0 = fmaxf(mx0, __shfl_xor_sync(0xFFFFFFFFu, mx0, 2));
        mx1 = fmaxf(mx1, __shfl_xor_sync(0xFFFFFFFFu, mx1, 1));
        mx1 = fmaxf(mx1, __shfl_xor_sync(0xFFFFFFFFu, mx1, 2));
        const float mN0 = fmaxf(rM0, mx0), mN1 = fmaxf(rM1, mx1);
        const float corr0 = __expf(rM0 - mN0), corr1 = __expf(rM1 - mN1);
        rM0 = mN0; rM1 = mN1;

        float sum0 = 0.f, sum1 = 0.f;
        uint32_t Ph[4][4], Pl[4][4];
#pragma unroll
        for (int jj = 0; jj < 8; jj++) {
            float e0 = __expf(sf[jj][0] - mN0);
            float e1 = __expf(sf[jj][1] - mN0);
            float e2 = __expf(sf[jj][2] - mN1);
            float e3 = __expf(sf[jj][3] - mN1);
            sum0 += e0 + e1;
            sum1 += e2 + e3;
            __half h0 = __float2half_rn(e0), h1 = __float2half_rn(e1);
            __half h2 = __float2half_rn(e2), h3 = __float2half_rn(e3);
            const int kk = jj >> 1, q = (jj & 1) * 2;
            Ph[kk][q + 0] = pack_h2(h0, h1);
            Ph[kk][q + 1] = pack_h2(h2, h3);
            Pl[kk][q + 0] = pack_h2(__float2half_rn(e0 - __half2float(h0)),
                                    __float2half_rn(e1 - __half2float(h1)));
            Pl[kk][q + 1] = pack_h2(__float2half_rn(e2 - __half2float(h2)),
                                    __float2half_rn(e3 - __half2float(h3)));
        }
        sum0 += __shfl_xor_sync(0xFFFFFFFFu, sum0, 1);
        sum0 += __shfl_xor_sync(0xFFFFFFFFu, sum0, 2);
        sum1 += __shfl_xor_sync(0xFFFFFFFFu, sum1, 1);
        sum1 += __shfl_xor_sync(0xFFFFFFFFu, sum1, 2);
        rL0 = rL0 * corr0 + sum0;
        rL1 = rL1 * corr1 + sum1;

#pragma unroll
        for (int nf = 0; nf < 16; nf++) {
            o[nf][0] *= corr0; o[nf][1] *= corr0;
            o[nf][2] *= corr1; o[nf][3] *= corr1;
        }

        // ---- O += P V (3-term), P from registers ----
#pragma unroll
        for (int kk = 0; kk < 4; kk++) {
            const int vk = kk * 16;
#pragma unroll
            for (int vx = 0; vx < 8; vx++) {
                const int d0 = vx * 16;
                uint32_t vo = (uint32_t)(((vk + lrow) * LDQ + d0 + lcolh) * 2);
                uint32_t vh[4], vl[4];
                LDSM_X4T(vh[0], vh[1], vh[2], vh[3], vh_b + vo);
                LDSM_X4T(vl[0], vl[1], vl[2], vl[3], vl_b + vo);
                MMA16816(o[2 * vx], Ph[kk][0], Ph[kk][1], Ph[kk][2], Ph[kk][3], vh[0], vh[1]);
                MMA16816(o[2 * vx], Pl[kk][0], Pl[kk][1], Pl[kk][2], Pl[kk][3], vh[0], vh[1]);
                MMA16816(o[2 * vx], Ph[kk][0], Ph[kk][1], Ph[kk][2], Ph[kk][3], vl[0], vl[1]);
                MMA16816(o[2 * vx + 1], Ph[kk][0], Ph[kk][1], Ph[kk][2], Ph[kk][3], vh[2], vh[3]);
                MMA16816(o[2 * vx + 1], Pl[kk][0], Pl[kk][1], Pl[kk][2], Pl[kk][3], vh[2], vh[3]);
                MMA16816(o[2 * vx + 1], Ph[kk][0], Ph[kk][1], Ph[kk][2], Ph[kk][3], vl[2], vl[3]);
            }
        }
    }

    // ---- normalize + store fp16 hi/lo ----
    const float il0 = 1.f / rL0, il1 = 1.f / rL1;
#pragma unroll
    for (int nf = 0; nf < 16; nf++) {
        const int d = h * DH + nf * 8 + c0l;
        float f0 = o[nf][0] * il0, f1 = o[nf][1] * il0;
        float f2 = o[nf][2] * il1, f3 = o[nf][3] * il1;
        __half h0 = __float2half_rn(f0), h1 = __float2half_rn(f1);
        __half h2 = __float2half_rn(f2), h3 = __float2half_rn(f3);
        size_t o0 = (size_t)gq0 * HID_DIM + d;
        size_t o1 = (size_t)gq1 * HID_DIM + d;
        *(__half2*)(Oh + o0) = __halves2half2(h0, h1);
        *(__half2*)(Oh + o1) = __halves2half2(h2, h3);
        *(__half2*)(Ol + o0) = __halves2half2(
            __float2half_rn(f0 - __half2float(h0)),
            __float2half_rn(f1 - __half2float(h1)));
        *(__half2*)(Ol + o1) = __halves2half2(
            __float2half_rn(f2 - __half2float(h2)),
            __float2half_rn(f3 - __half2float(h3)));
    }
}

// ---------------------------------------------------------------------------
// Orchestration
// ---------------------------------------------------------------------------
extern "C" void kernel_launch(void* const* d_in, const int* in_sizes, int n_in,
                              void* d_out, int out_size)
{
    const float* hidden = (const float*)d_in[0];
    const float* wq = (const float*)d_in[2];
    const float* wk = (const float*)d_in[3];
    const float* wv = (const float*)d_in[4];
    const float* wo = (const float*)d_in[5];
    float* out = (float*)d_out;

    __half *hh, *hl, *qkvh, *qkvl, *ath, *atl, *wqkv, *wot;
    cudaGetSymbolAddress((void**)&hh, g_hid_hi);    cudaGetSymbolAddress((void**)&hl, g_hid_lo);
    cudaGetSymbolAddress((void**)&qkvh, g_qkv_hi);  cudaGetSymbolAddress((void**)&qkvl, g_qkv_lo);
    cudaGetSymbolAddress((void**)&ath, g_at_hi);    cudaGetSymbolAddress((void**)&atl, g_at_lo);
    cudaGetSymbolAddress((void**)&wqkv, g_wqkvT);   cudaGetSymbolAddress((void**)&wot, g_woT);

    cudaFuncSetAttribute(attn_mma_kernel, cudaFuncAttributeMaxDynamicSharedMemorySize, ATT_SMEM);
    cudaFuncSetAttribute(gemm_fp16x2_kernel, cudaFuncAttributeMaxDynamicSharedMemorySize, GEMM_SMEM);

    conv_hilo_kernel<<<(S_LEN * HID_DIM) / 1024, 256>>>(hidden, hh, hl, S_LEN * HID_DIM);
    dim3 tb(32, 8);
    conv_t_kernel<<<dim3(HID_DIM / 32, HID_DIM / 32), tb>>>(wq, wqkv, HID_DIM, HID_DIM);
    conv_t_kernel<<<dim3(KVW / 32, HID_DIM / 32), tb>>>(
        wk, wqkv + (size_t)HID_DIM * HID_DIM, HID_DIM, KVW);
    conv_t_kernel<<<dim3(KVW / 32, HID_DIM / 32), tb>>>(
        wv, wqkv + (size_t)(HID_DIM + KVW) * HID_DIM, HID_DIM, KVW);
    conv_t_kernel<<<dim3(HID_DIM / 32, HID_DIM / 32), tb>>>(wo, wot, HID_DIM, HID_DIM);

    gemm_fp16x2_kernel<<<dim3(QKVW / 128, S_LEN / 256), 256, GEMM_SMEM>>>(
        hh, hl, wqkv, nullptr, qkvh, qkvl, S_LEN, QKVW, HID_DIM);

    attn_mma_kernel<<<dim3(16, NH), 256, ATT_SMEM>>>(qkvh, qkvl, ath, atl);

    gemm_fp16x2_kernel<<<dim3(HID_DIM / 128, S_LEN / 256), 256, GEMM_SMEM>>>(
        ath, atl, wot, out, nullptr, nullptr, S_LEN, HID_DIM, HID_DIM);
}

// round 9
// speedup vs baseline: 6.9853x; 1.1001x over previous
#include <cuda_runtime.h>
#include <cuda_fp16.h>
#include <cstdint>
#include <math.h>

#define S_LEN 2048
#define HID_DIM 4096
#define NH 32
#define NKV 8
#define DH 128
#define KVW (NKV * DH)     // 1024
#define QKVW 6144          // fused Q(4096) + K(1024) + V(1024) width

// ---------------------------------------------------------------------------
// Scratch (device globals: allocation-free)
// ---------------------------------------------------------------------------
__device__ __half g_hid_hi[S_LEN * HID_DIM];
__device__ __half g_hid_lo[S_LEN * HID_DIM];
__device__ __half g_qkv_hi[S_LEN * QKVW];
__device__ __half g_qkv_lo[S_LEN * QKVW];
__device__ __half g_at_hi[S_LEN * HID_DIM];
__device__ __half g_at_lo[S_LEN * HID_DIM];
__device__ __half g_wqkvT[QKVW * HID_DIM];
__device__ __half g_woT[HID_DIM * HID_DIM];

// ---------------------------------------------------------------------------
// PTX helpers (baseline sm_80 PTX — safe on compute_103)
// ---------------------------------------------------------------------------
__device__ __forceinline__ uint32_t smem_u32(const void* p) {
    return (uint32_t)__cvta_generic_to_shared(p);
}
#define CP_ASYNC16(sa, gp) \
    asm volatile("cp.async.cg.shared.global [%0], [%1], 16;" :: "r"(sa), "l"(gp))
#define CP_COMMIT() asm volatile("cp.async.commit_group;" ::: "memory")
#define CP_WAIT(n)  asm volatile("cp.async.wait_group %0;" :: "n"(n) : "memory")

#define LDSM_X4(r0, r1, r2, r3, a) \
    asm volatile("ldmatrix.sync.aligned.m8n8.x4.shared.b16 {%0,%1,%2,%3},[%4];" \
        : "=r"(r0), "=r"(r1), "=r"(r2), "=r"(r3) : "r"(a))
#define LDSM_X4T(r0, r1, r2, r3, a) \
    asm volatile("ldmatrix.sync.aligned.m8n8.x4.trans.shared.b16 {%0,%1,%2,%3},[%4];" \
        : "=r"(r0), "=r"(r1), "=r"(r2), "=r"(r3) : "r"(a))
#define MMA16816(d, a0, a1, a2, a3, b0, b1) \
    asm volatile("mma.sync.aligned.m16n8k16.row.col.f32.f16.f16.f32 " \
        "{%0,%1,%2,%3},{%4,%5,%6,%7},{%8,%9},{%0,%1,%2,%3};" \
        : "+f"((d)[0]), "+f"((d)[1]), "+f"((d)[2]), "+f"((d)[3]) \
        : "r"(a0), "r"(a1), "r"(a2), "r"(a3), "r"(b0), "r"(b1))

__device__ __forceinline__ uint32_t pack_h2(__half a, __half b) {
    __half2 h = __halves2half2(a, b);
    return *(uint32_t*)&h;
}

// ---------------------------------------------------------------------------
// Split fp32 -> (hi, lo) fp16, elementwise
// ---------------------------------------------------------------------------
__global__ void conv_hilo_kernel(const float* __restrict__ x,
                                 __half* __restrict__ hi,
                                 __half* __restrict__ lo, int n)
{
    int i = (blockIdx.x * blockDim.x + threadIdx.x) * 4;
    if (i >= n) return;
    float4 v = *(const float4*)(x + i);
    __half h0 = __float2half_rn(v.x);
    __half h1 = __float2half_rn(v.y);
    __half h2 = __float2half_rn(v.z);
    __half h3 = __float2half_rn(v.w);
    __half l0 = __float2half_rn(v.x - __half2float(h0));
    __half l1 = __float2half_rn(v.y - __half2float(h1));
    __half l2 = __float2half_rn(v.z - __half2float(h2));
    __half l3 = __float2half_rn(v.w - __half2float(h3));
    __half2* hp = (__half2*)(hi + i);
    __half2* lp = (__half2*)(lo + i);
    hp[0] = __half2(h0, h1); hp[1] = __half2(h2, h3);
    lp[0] = __half2(l0, l1); lp[1] = __half2(l2, l3);
}

// ---------------------------------------------------------------------------
// Transpose + round: B[K,N] fp32 -> T[N,K] fp16
// ---------------------------------------------------------------------------
__global__ void conv_t_kernel(const float* __restrict__ B,
                              __half* __restrict__ T, int K, int N)
{
    __shared__ float t[32][33];
    const int n0 = blockIdx.x * 32, k0 = blockIdx.y * 32;
    const int tx = threadIdx.x, ty = threadIdx.y;
#pragma unroll
    for (int i = 0; i < 32; i += 8)
        t[ty + i][tx] = B[(size_t)(k0 + ty + i) * N + n0 + tx];
    __syncthreads();
#pragma unroll
    for (int i = 0; i < 32; i += 8) {
        size_t o = (size_t)(n0 + ty + i) * K + k0 + tx;
        T[o] = __float2half_rn(t[tx][ty + i]);
    }
}

// ---------------------------------------------------------------------------
// fp16 split-A GEMM: D = Ah*B + Al*B.  B transposed [N,K] fp16.
// CTA tile 128x128, 8 warps (warp tile 32x64), k32, 3-stage cp.async,
// __launch_bounds__(256,2) -> 2 CTAs/SM, <=128 regs, 4 warps/SMSP.
// ---------------------------------------------------------------------------
#define TLD 40
#define SMAT_BYTES (128 * TLD * 2)            // 10240 (one 128x32 fp16 tile)
#define STG_BYTES (3 * SMAT_BYTES)            // 30720 (Ah, Al, B)
#define GEMM_SMEM (3 * STG_BYTES)             // 92160

__global__ void __launch_bounds__(256, 2) gemm_fp16x2_kernel(
    const __half* __restrict__ Ahi, const __half* __restrict__ Alo,
    const __half* __restrict__ Bh,
    float* __restrict__ Cf,
    __half* __restrict__ Chi, __half* __restrict__ Clo,
    int M, int N, int K)
{
    extern __shared__ char smem[];
    const uint32_t sb = smem_u32(smem);
    const int tid = threadIdx.x;
    const int lane = tid & 31, wid = tid >> 5;
    const int wm = wid & 3, wn = wid >> 2;
    const int m0 = blockIdx.y * 128, n0 = blockIdx.x * 128;

    auto issue = [&](int it) {
        const int s = it % 3;
        const int k0 = it * 32;
        const uint32_t st = sb + s * STG_BYTES;
#pragma unroll
        for (int i = 0; i < 2; i++) {
            int c = tid + i * 256;           // 0..511
            int row = c >> 2, seg = c & 3;
            uint32_t so = (uint32_t)((row * TLD + seg * 8) * 2);
            size_t gA = (size_t)(m0 + row) * K + k0 + seg * 8;
            size_t gB = (size_t)(n0 + row) * K + k0 + seg * 8;
            CP_ASYNC16(st + so, (const void*)(Ahi + gA));
            CP_ASYNC16(st + SMAT_BYTES + so, (const void*)(Alo + gA));
            CP_ASYNC16(st + 2 * SMAT_BYTES + so, (const void*)(Bh + gB));
        }
        CP_COMMIT();
    };

    float acc[2][8][4];
#pragma unroll
    for (int mi = 0; mi < 2; mi++)
#pragma unroll
        for (int nj = 0; nj < 8; nj++)
#pragma unroll
            for (int r = 0; r < 4; r++) acc[mi][nj][r] = 0.f;

    const int nIter = K >> 5;
    issue(0);
    issue(1);

    for (int it = 0; it < nIter; ++it) {
        if (it + 1 < nIter) { CP_WAIT(1); } else { CP_WAIT(0); }
        __syncthreads();
        if (it + 2 < nIter) issue(it + 2);

        const uint32_t st = sb + (it % 3) * STG_BYTES;
        const uint32_t ah_b = st;
        const uint32_t al_b = st + SMAT_BYTES;
        const uint32_t bh_b = st + 2 * SMAT_BYTES;

#pragma unroll
        for (int ks = 0; ks < 2; ks++) {
            uint32_t ah[2][4], al[2][4];
            const int arow = wm * 32 + (lane & 15);
            const int acol = ks * 16 + (lane >> 4) * 8;
#pragma unroll
            for (int mi = 0; mi < 2; mi++) {
                uint32_t off = (uint32_t)(((arow + mi * 16) * TLD + acol) * 2);
                LDSM_X4(ah[mi][0], ah[mi][1], ah[mi][2], ah[mi][3], ah_b + off);
                LDSM_X4(al[mi][0], al[mi][1], al[mi][2], al[mi][3], al_b + off);
            }
            const int brow = wn * 64 + (lane & 7) + ((lane >> 4) << 3);
            const int bcol = ks * 16 + (((lane >> 3) & 1) << 3);
#pragma unroll
            for (int nt = 0; nt < 4; nt++) {
                uint32_t off = (uint32_t)(((brow + nt * 16) * TLD + bcol) * 2);
                uint32_t bh[4];
                LDSM_X4(bh[0], bh[1], bh[2], bh[3], bh_b + off);
#pragma unroll
                for (int mi = 0; mi < 2; mi++) {
                    MMA16816(acc[mi][2 * nt], ah[mi][0], ah[mi][1], ah[mi][2], ah[mi][3], bh[0], bh[1]);
                    MMA16816(acc[mi][2 * nt], al[mi][0], al[mi][1], al[mi][2], al[mi][3], bh[0], bh[1]);
                    MMA16816(acc[mi][2 * nt + 1], ah[mi][0], ah[mi][1], ah[mi][2], ah[mi][3], bh[2], bh[3]);
                    MMA16816(acc[mi][2 * nt + 1], al[mi][0], al[mi][1], al[mi][2], al[mi][3], bh[2], bh[3]);
                }
            }
        }
    }

    const int er = lane >> 2, ec = (lane & 3) * 2;
#pragma unroll
    for (int mi = 0; mi < 2; mi++) {
        const int gr = m0 + wm * 32 + mi * 16 + er;
#pragma unroll
        for (int nj = 0; nj < 8; nj++) {
            const int gc = n0 + wn * 64 + nj * 8 + ec;
            if (Chi) {
#pragma unroll
                for (int half_ = 0; half_ < 2; half_++) {
                    float f0 = acc[mi][nj][half_ * 2 + 0];
                    float f1 = acc[mi][nj][half_ * 2 + 1];
                    __half h0 = __float2half_rn(f0);
                    __half h1 = __float2half_rn(f1);
                    __half l0 = __float2half_rn(f0 - __half2float(h0));
                    __half l1 = __float2half_rn(f1 - __half2float(h1));
                    size_t o = (size_t)(gr + half_ * 8) * N + gc;
                    *(__half2*)(Chi + o) = __half2(h0, h1);
                    *(__half2*)(Clo + o) = __half2(l0, l1);
                }
            } else {
                *(float2*)(Cf + (size_t)gr * N + gc) =
                    make_float2(acc[mi][nj][0], acc[mi][nj][1]);
                *(float2*)(Cf + (size_t)(gr + 8) * N + gc) =
                    make_float2(acc[mi][nj][2], acc[mi][nj][3]);
            }
        }
    }
}

// ---------------------------------------------------------------------------
// Register-resident FA2 attention (unchanged from R8): 128-query tile/CTA,
// warp owns 16 rows x full 64-key width, warp-local softmax, 3-term comp.
// ---------------------------------------------------------------------------
#define LDQ 136
#define AQH 0
#define AQL 34816
#define AKV 69632
#define AMAT 17408
#define AKV_STG (4 * AMAT)           // 69632
#define ATT_SMEM (AKV + 2 * AKV_STG) // 208896

__global__ void __launch_bounds__(256, 1) attn_mma_kernel(
    const __half* __restrict__ QKVh, const __half* __restrict__ QKVl,
    __half* __restrict__ Oh, __half* __restrict__ Ol)
{
    extern __shared__ char sm[];
    const uint32_t sb = smem_u32(sm);
    const int tid = threadIdx.x;
    const int wid = tid >> 5, lane = tid & 31;
    const int qt = 15 - (int)blockIdx.x;     // heavy tiles first
    const int h = blockIdx.y;
    const int kvh = h >> 2;
    const int m0 = qt * 128;
    const int wrow = wid * 16;
    const float scale = 0.08838834764831845f;

    const int koff = HID_DIM + kvh * DH;
    const int voff = HID_DIM + KVW + kvh * DH;

    auto kv_issue = [&](int jt, int s) {
        const uint32_t st = sb + AKV + s * AKV_STG;
#pragma unroll
        for (int i = 0; i < 4; i++) {
            int idx = tid + i * 256;
            int row = idx >> 4, seg = idx & 15;
            uint32_t so = (uint32_t)((row * LDQ + seg * 8) * 2);
            size_t gK = (size_t)(jt * 64 + row) * QKVW + koff + seg * 8;
            size_t gV = (size_t)(jt * 64 + row) * QKVW + voff + seg * 8;
            CP_ASYNC16(st + 0 * AMAT + so, (const void*)(QKVh + gK));
            CP_ASYNC16(st + 1 * AMAT + so, (const void*)(QKVl + gK));
            CP_ASYNC16(st + 2 * AMAT + so, (const void*)(QKVh + gV));
            CP_ASYNC16(st + 3 * AMAT + so, (const void*)(QKVl + gV));
        }
        CP_COMMIT();
    };

    kv_issue(0, 0);

    {
        __half* qh_s = (__half*)(sm + AQH);
        __half* ql_s = (__half*)(sm + AQL);
#pragma unroll
        for (int i = 0; i < 8; i++) {
            int idx = tid + i * 256;
            int row = idx >> 4, seg = idx & 15;
            size_t g = (size_t)(m0 + row) * QKVW + h * DH + seg * 8;
            *(uint4*)(qh_s + row * LDQ + seg * 8) = *(const uint4*)(QKVh + g);
            *(uint4*)(ql_s + row * LDQ + seg * 8) = *(const uint4*)(QKVl + g);
        }
    }

    float o[16][4];
#pragma unroll
    for (int nf = 0; nf < 16; nf++)
#pragma unroll
        for (int r = 0; r < 4; r++) o[nf][r] = 0.f;
    float rM0 = -1e30f, rM1 = -1e30f, rL0 = 0.f, rL1 = 0.f;

    const int r0l = lane >> 2, c0l = (lane & 3) * 2;
    const int lrow = lane & 15, lcolh = (lane >> 4) * 8;
    const int gq0 = m0 + wrow + r0l, gq1 = gq0 + 8;
    const int nIter = 2 * qt + 2;

    for (int jt = 0; jt < nIter; jt++) {
        const int s = jt & 1;
        CP_WAIT(0);
        __syncthreads();
        if (jt + 1 < nIter) kv_issue(jt + 1, s ^ 1);

        const uint32_t kh_b = sb + AKV + s * AKV_STG;
        const uint32_t kl_b = kh_b + AMAT;
        const uint32_t vh_b = kh_b + 2 * AMAT;
        const uint32_t vl_b = kh_b + 3 * AMAT;

        float sf[8][4];
#pragma unroll
        for (int jj = 0; jj < 8; jj++)
#pragma unroll
            for (int r = 0; r < 4; r++) sf[jj][r] = 0.f;

#pragma unroll
        for (int ks = 0; ks < 8; ks++) {
            const int k0 = ks * 16;
            uint32_t aoff = (uint32_t)(((wrow + lrow) * LDQ + k0 + lcolh) * 2);
            uint32_t qh[4], ql[4];
            LDSM_X4(qh[0], qh[1], qh[2], qh[3], sb + AQH + aoff);
            LDSM_X4(ql[0], ql[1], ql[2], ql[3], sb + AQL + aoff);
#pragma unroll
            for (int jb = 0; jb < 4; jb++) {
                uint32_t boff = (uint32_t)(((jb * 16 + lrow) * LDQ + k0 + lcolh) * 2);
                uint32_t bh[4], bl[4];
                LDSM_X4(bh[0], bh[1], bh[2], bh[3], kh_b + boff);
                LDSM_X4(bl[0], bl[1], bl[2], bl[3], kl_b + boff);
                MMA16816(sf[2 * jb], qh[0], qh[1], qh[2], qh[3], bh[0], bh[2]);
                MMA16816(sf[2 * jb], qh[0], qh[1], qh[2], qh[3], bl[0], bl[2]);
                MMA16816(sf[2 * jb], ql[0], ql[1], ql[2], ql[3], bh[0], bh[2]);
                MMA16816(sf[2 * jb + 1], qh[0], qh[1], qh[2], qh[3], bh[1], bh[3]);
                MMA16816(sf[2 * jb + 1], qh[0], qh[1], qh[2], qh[3], bl[1], bl[3]);
                MMA16816(sf[2 * jb + 1], ql[0], ql[1], ql[2], ql[3], bh[1], bh[3]);
            }
        }

        const int jn0 = jt * 64;
        float mx0 = -1e30f, mx1 = -1e30f;
#pragma unroll
        for (int jj = 0; jj < 8; jj++) {
            int cb = jn0 + jj * 8 + c0l;
            sf[jj][0] = (cb > gq0) ? -1e30f : sf[jj][0] * scale;
            sf[jj][1] = (cb + 1 > gq0) ? -1e30f : sf[jj][1] * scale;
            sf[jj][2] = (cb > gq1) ? -1e30f : sf[jj][2] * scale;
            sf[jj][3] = (cb + 1 > gq1) ? -1e30f : sf[jj][3] * scale;
            mx0 = fmaxf(mx0, fmaxf(sf[jj][0], sf[jj][1]));
            mx1 = fmaxf(mx1, fmaxf(sf[jj][2], sf[jj][3]));
        }
        mx0 = fmaxf(mx0, __shfl_xor_sync(0xFFFFFFFFu, mx0, 1));
        mx0 = fmaxf(mx0, __shfl_xor_sync(0xFFFFFFFFu, mx0, 2));
        mx1 = fmaxf(mx1, __shfl_xor_sync(0xFFFFFFFFu, mx1, 1));
        mx1 = fmaxf(mx1, __shfl_xor_sync(0xFFFFFFFFu, mx1, 2));
        const float mN0 = fmaxf(rM0, mx0), mN1 = fmaxf(rM1, mx1);
        const float corr0 = __expf(rM0 - mN0), corr1 = __expf(rM1 - mN1);
        rM0 = mN0; rM1 = mN1;

        float sum0 = 0.f, sum1 = 0.f;
        uint32_t Ph[4][4], Pl[4][4];
#pragma unroll
        for (int jj = 0; jj < 8; jj++) {
            float e0 = __expf(sf[jj][0] - mN0);
            float e1 = __expf(sf[jj][1] - mN0);
            float e2 = __expf(sf[jj][2] - mN1);
            float e3 = __expf(sf[jj][3] - mN1);
            sum0 += e0 + e1;
            sum1 += e2 + e3;
            __half h0 = __float2half_rn(e0), h1 = __float2half_rn(e1);
            __half h2 = __float2half_rn(e2), h3 = __float2half_rn(e3);
            const int kk = jj >> 1, q = (jj & 1) * 2;
            Ph[kk][q + 0] = pack_h2(h0, h1);
            Ph[kk][q + 1] = pack_h2(h2, h3);
            Pl[kk][q + 0] = pack_h2(__float2half_rn(e0 - __half2float(h0)),
                                    __float2half_rn(e1 - __half2float(h1)));
            Pl[kk][q + 1] = pack_h2(__float2half_rn(e2 - __half2float(h2)),
                                    __float2half_rn(e3 - __half2float(h3)));
        }
        sum0 += __shfl_xor_sync(0xFFFFFFFFu, sum0, 1);
        sum0 += __shfl_xor_sync(0xFFFFFFFFu, sum0, 2);
        sum1 += __shfl_xor_sync(0xFFFFFFFFu, sum1, 1);
        sum1 += __shfl_xor_sync(0xFFFFFFFFu, sum1, 2);
        rL0 = rL0 * corr0 + sum0;
        rL1 = rL1 * corr1 + sum1;

#pragma unroll
        for (int nf = 0; nf < 16; nf++) {
            o[nf][0] *= corr0; o[nf][1] *= corr0;
            o[nf][2] *= corr1; o[nf][3] *= corr1;
        }

#pragma unroll
        for (int kk = 0; kk < 4; kk++) {
            const int vk = kk * 16;
#pragma unroll
            for (int vx = 0; vx < 8; vx++) {
                const int d0 = vx * 16;
                uint32_t vo = (uint32_t)(((vk + lrow) * LDQ + d0 + lcolh) * 2);
                uint32_t vh[4], vl[4];
                LDSM_X4T(vh[0], vh[1], vh[2], vh[3], vh_b + vo);
                LDSM_X4T(vl[0], vl[1], vl[2], vl[3], vl_b + vo);
                MMA16816(o[2 * vx], Ph[kk][0], Ph[kk][1], Ph[kk][2], Ph[kk][3], vh[0], vh[1]);
                MMA16816(o[2 * vx], Pl[kk][0], Pl[kk][1], Pl[kk][2], Pl[kk][3], vh[0], vh[1]);
                MMA16816(o[2 * vx], Ph[kk][0], Ph[kk][1], Ph[kk][2], Ph[kk][3], vl[0], vl[1]);
                MMA16816(o[2 * vx + 1], Ph[kk][0], Ph[kk][1], Ph[kk][2], Ph[kk][3], vh[2], vh[3]);
                MMA16816(o[2 * vx + 1], Pl[kk][0], Pl[kk][1], Pl[kk][2], Pl[kk][3], vh[2], vh[3]);
                MMA16816(o[2 * vx + 1], Ph[kk][0], Ph[kk][1], Ph[kk][2], Ph[kk][3], vl[2], vl[3]);
            }
        }
    }

    const float il0 = 1.f / rL0, il1 = 1.f / rL1;
#pragma unroll
    for (int nf = 0; nf < 16; nf++) {
        const int d = h * DH + nf * 8 + c0l;
        float f0 = o[nf][0] * il0, f1 = o[nf][1] * il0;
        float f2 = o[nf][2] * il1, f3 = o[nf][3] * il1;
        __half h0 = __float2half_rn(f0), h1 = __float2half_rn(f1);
        __half h2 = __float2half_rn(f2), h3 = __float2half_rn(f3);
        size_t o0 = (size_t)gq0 * HID_DIM + d;
        size_t o1 = (size_t)gq1 * HID_DIM + d;
        *(__half2*)(Oh + o0) = __halves2half2(h0, h1);
        *(__half2*)(Oh + o1) = __halves2half2(h2, h3);
        *(__half2*)(Ol + o0) = __halves2half2(
            __float2half_rn(f0 - __half2float(h0)),
            __float2half_rn(f1 - __half2float(h1)));
        *(__half2*)(Ol + o1) = __halves2half2(
            __float2half_rn(f2 - __half2float(h2)),
            __float2half_rn(f3 - __half2float(h3)));
    }
}

// ---------------------------------------------------------------------------
// Orchestration
// ---------------------------------------------------------------------------
extern "C" void kernel_launch(void* const* d_in, const int* in_sizes, int n_in,
                              void* d_out, int out_size)
{
    const float* hidden = (const float*)d_in[0];
    const float* wq = (const float*)d_in[2];
    const float* wk = (const float*)d_in[3];
    const float* wv = (const float*)d_in[4];
    const float* wo = (const float*)d_in[5];
    float* out = (float*)d_out;

    __half *hh, *hl, *qkvh, *qkvl, *ath, *atl, *wqkv, *wot;
    cudaGetSymbolAddress((void**)&hh, g_hid_hi);    cudaGetSymbolAddress((void**)&hl, g_hid_lo);
    cudaGetSymbolAddress((void**)&qkvh, g_qkv_hi);  cudaGetSymbolAddress((void**)&qkvl, g_qkv_lo);
    cudaGetSymbolAddress((void**)&ath, g_at_hi);    cudaGetSymbolAddress((void**)&atl, g_at_lo);
    cudaGetSymbolAddress((void**)&wqkv, g_wqkvT);   cudaGetSymbolAddress((void**)&wot, g_woT);

    cudaFuncSetAttribute(attn_mma_kernel, cudaFuncAttributeMaxDynamicSharedMemorySize, ATT_SMEM);
    cudaFuncSetAttribute(gemm_fp16x2_kernel, cudaFuncAttributeMaxDynamicSharedMemorySize, GEMM_SMEM);

    conv_hilo_kernel<<<(S_LEN * HID_DIM) / 1024, 256>>>(hidden, hh, hl, S_LEN * HID_DIM);
    dim3 tb(32, 8);
    conv_t_kernel<<<dim3(HID_DIM / 32, HID_DIM / 32), tb>>>(wq, wqkv, HID_DIM, HID_DIM);
    conv_t_kernel<<<dim3(KVW / 32, HID_DIM / 32), tb>>>(
        wk, wqkv + (size_t)HID_DIM * HID_DIM, HID_DIM, KVW);
    conv_t_kernel<<<dim3(KVW / 32, HID_DIM / 32), tb>>>(
        wv, wqkv + (size_t)(HID_DIM + KVW) * HID_DIM, HID_DIM, KVW);
    conv_t_kernel<<<dim3(HID_DIM / 32, HID_DIM / 32), tb>>>(wo, wot, HID_DIM, HID_DIM);

    gemm_fp16x2_kernel<<<dim3(QKVW / 128, S_LEN / 128), 256, GEMM_SMEM>>>(
        hh, hl, wqkv, nullptr, qkvh, qkvl, S_LEN, QKVW, HID_DIM);

    attn_mma_kernel<<<dim3(16, NH), 256, ATT_SMEM>>>(qkvh, qkvl, ath, atl);

    gemm_fp16x2_kernel<<<dim3(HID_DIM / 128, S_LEN / 128), 256, GEMM_SMEM>>>(
        ath, atl, wot, out, nullptr, nullptr, S_LEN, HID_DIM, HID_DIM);
}